// round 4
// baseline (speedup 1.0000x reference)
#include <cuda_runtime.h>
#include <cuda_bf16.h>
#include <cstdint>

#define D_MODEL 1280
#define SEQ     1024
#define N_BF    8
#define N_FR    4
#define N_HEADS 20
#define HDIM    64
#define M_TOT   (N_BF*SEQ)   // 8192

// Scratch (allocation-free rule: device globals). All bf16.
__device__ __nv_bfloat16 g_q[(size_t)M_TOT * D_MODEL];
__device__ __nv_bfloat16 g_k[(size_t)M_TOT * D_MODEL];
__device__ __nv_bfloat16 g_v[(size_t)M_TOT * D_MODEL];
__device__ __nv_bfloat16 g_attn[(size_t)M_TOT * D_MODEL];

__device__ __forceinline__ uint32_t packbf(float lo, float hi) {
    __nv_bfloat162 h = __floats2bfloat162_rn(lo, hi);
    return *reinterpret_cast<uint32_t*>(&h);
}

__device__ __forceinline__ void mma_bf16(float d[4], const uint32_t a[4], const uint32_t b[2]) {
    asm volatile(
        "mma.sync.aligned.m16n8k16.row.col.f32.bf16.bf16.f32 "
        "{%0,%1,%2,%3}, {%4,%5,%6,%7}, {%8,%9}, {%0,%1,%2,%3};\n"
        : "+f"(d[0]), "+f"(d[1]), "+f"(d[2]), "+f"(d[3])
        : "r"(a[0]), "r"(a[1]), "r"(a[2]), "r"(a[3]),
          "r"(b[0]), "r"(b[1]));
}

// ---------------------------------------------------------------------------
// C[M,N] = A[M,K] @ W[K,N] + bias (+ residual). bf16 mma, 128x128x32 tiles.
// A may be fp32 (converted on stage) or bf16 (raw copy). C fp32 or bf16.
// ---------------------------------------------------------------------------
template<bool A_BF16, bool OUT_BF16, bool ADD_RES>
__global__ __launch_bounds__(256, 2)
void gemm_kernel(const void* __restrict__ Ap, const float* __restrict__ W,
                 const float* __restrict__ bias, const float* __restrict__ res,
                 void* __restrict__ Cp, int M, int N, int K)
{
    __shared__ __nv_bfloat16 As[128][40];
    __shared__ __nv_bfloat16 Bs[128][40];   // Bs[n][k]

    const int bm = blockIdx.y, bn = blockIdx.x;
    const int tid = threadIdx.x;
    const int warp = tid >> 5, lane = tid & 31;
    const int wm = warp >> 2, wn = warp & 3;     // 2x4 warp grid, each 64x32
    const int gid = lane >> 2, tig = lane & 3;

    float acc[4][4][4];
    #pragma unroll
    for (int mt = 0; mt < 4; mt++)
        #pragma unroll
        for (int nt = 0; nt < 4; nt++)
            #pragma unroll
            for (int i = 0; i < 4; i++) acc[mt][nt][i] = 0.f;

    for (int kt = 0; kt < K; kt += 32) {
        // Stage A
        if (A_BF16) {
            const __nv_bfloat16* A = (const __nv_bfloat16*)Ap;
            #pragma unroll
            for (int i = 0; i < 2; i++) {
                int idx = tid + i * 256;
                int r = idx >> 2, c = (idx & 3) * 8;
                const __nv_bfloat16* src = A + (size_t)(bm * 128 + r) * K + kt + c;
                *reinterpret_cast<uint4*>(&As[r][c]) = *reinterpret_cast<const uint4*>(src);
            }
        } else {
            const float* A = (const float*)Ap;
            #pragma unroll
            for (int i = 0; i < 4; i++) {
                int idx = tid + i * 256;
                int r = idx >> 3, c = (idx & 7) * 4;
                float4 v = *reinterpret_cast<const float4*>(A + (size_t)(bm * 128 + r) * K + kt + c);
                *reinterpret_cast<__nv_bfloat162*>(&As[r][c])     = __floats2bfloat162_rn(v.x, v.y);
                *reinterpret_cast<__nv_bfloat162*>(&As[r][c + 2]) = __floats2bfloat162_rn(v.z, v.w);
            }
        }
        // Stage W transposed -> Bs[n][k]
        #pragma unroll
        for (int i = 0; i < 4; i++) {
            int idx = tid + i * 256;
            int r = idx >> 5, c = (idx & 31) * 4;
            float4 v = *reinterpret_cast<const float4*>(W + (size_t)(kt + r) * N + bn * 128 + c);
            Bs[c + 0][r] = __float2bfloat16_rn(v.x);
            Bs[c + 1][r] = __float2bfloat16_rn(v.y);
            Bs[c + 2][r] = __float2bfloat16_rn(v.z);
            Bs[c + 3][r] = __float2bfloat16_rn(v.w);
        }
        __syncthreads();

        #pragma unroll
        for (int kk = 0; kk < 32; kk += 16) {
            uint32_t aA[4][4];
            #pragma unroll
            for (int mt = 0; mt < 4; mt++) {
                int r = wm * 64 + mt * 16 + gid;
                aA[mt][0] = *reinterpret_cast<const uint32_t*>(&As[r][kk + 2 * tig]);
                aA[mt][1] = *reinterpret_cast<const uint32_t*>(&As[r + 8][kk + 2 * tig]);
                aA[mt][2] = *reinterpret_cast<const uint32_t*>(&As[r][kk + 2 * tig + 8]);
                aA[mt][3] = *reinterpret_cast<const uint32_t*>(&As[r + 8][kk + 2 * tig + 8]);
            }
            uint32_t bB[4][2];
            #pragma unroll
            for (int nt = 0; nt < 4; nt++) {
                int n = wn * 32 + nt * 8 + gid;
                bB[nt][0] = *reinterpret_cast<const uint32_t*>(&Bs[n][kk + 2 * tig]);
                bB[nt][1] = *reinterpret_cast<const uint32_t*>(&Bs[n][kk + 2 * tig + 8]);
            }
            #pragma unroll
            for (int mt = 0; mt < 4; mt++)
                #pragma unroll
                for (int nt = 0; nt < 4; nt++)
                    mma_bf16(acc[mt][nt], aA[mt], bB[nt]);
        }
        __syncthreads();
    }

    // Epilogue
    #pragma unroll
    for (int mt = 0; mt < 4; mt++) {
        int row = bm * 128 + wm * 64 + mt * 16 + gid;
        #pragma unroll
        for (int nt = 0; nt < 4; nt++) {
            int col = bn * 128 + wn * 32 + nt * 8 + 2 * tig;
            float b0 = bias[col], b1 = bias[col + 1];
            size_t i0 = (size_t)row * N + col;
            size_t i1 = i0 + 8 * (size_t)N;
            float v0 = acc[mt][nt][0] + b0, v1 = acc[mt][nt][1] + b1;
            float v2 = acc[mt][nt][2] + b0, v3 = acc[mt][nt][3] + b1;
            if (OUT_BF16) {
                __nv_bfloat16* C = (__nv_bfloat16*)Cp;
                *reinterpret_cast<__nv_bfloat162*>(C + i0) = __floats2bfloat162_rn(v0, v1);
                *reinterpret_cast<__nv_bfloat162*>(C + i1) = __floats2bfloat162_rn(v2, v3);
            } else {
                float* C = (float*)Cp;
                if (ADD_RES) { v0 += res[i0]; v1 += res[i0 + 1]; v2 += res[i1]; v3 += res[i1 + 1]; }
                C[i0] = v0; C[i0 + 1] = v1; C[i1] = v2; C[i1 + 1] = v3;
            }
        }
    }
}

// ---------------------------------------------------------------------------
// Flash attention over 2S keys, bf16 mma m16n8k16, P kept in registers
// (accumulator->A-fragment identity), V^T via ldmatrix.x4.trans.
// Block = (qtile 64 rows, head, bf). 4 warps.
// ---------------------------------------------------------------------------
__global__ __launch_bounds__(128)
void attn_kernel()
{
    __shared__ __nv_bfloat16 Qs[64][72];
    __shared__ __nv_bfloat16 Ks[64][72];
    __shared__ __nv_bfloat16 Vs[64][72];

    const int qt = blockIdx.x, h = blockIdx.y, bfi = blockIdx.z;
    const int bf0 = bfi & ~(N_FR - 1);
    const int tid = threadIdx.x;
    const int w = tid >> 5, lane = tid & 31;
    const int gid = lane >> 2, tig = lane & 3;

    // Stage Q tile, pre-scaled by 1/sqrt(64) = 0.125 (exact in bf16)
    {
        const __nv_bfloat162 sc = __floats2bfloat162_rn(0.125f, 0.125f);
        #pragma unroll
        for (int i = 0; i < 4; i++) {
            int idx = tid + i * 128;
            int r = idx >> 3, c = (idx & 7) * 8;
            const __nv_bfloat16* p = g_q + (size_t)(bfi * SEQ + qt * 64 + r) * D_MODEL + h * HDIM + c;
            uint4 v = *reinterpret_cast<const uint4*>(p);
            __nv_bfloat162* pv = reinterpret_cast<__nv_bfloat162*>(&v);
            #pragma unroll
            for (int j = 0; j < 4; j++) pv[j] = __hmul2(pv[j], sc);
            *reinterpret_cast<uint4*>(&Qs[r][c]) = v;
        }
    }
    __syncthreads();

    float oacc[8][4];
    #pragma unroll
    for (int nt = 0; nt < 8; nt++)
        #pragma unroll
        for (int i = 0; i < 4; i++) oacc[nt][i] = 0.f;
    float m0 = -3e38f, m1 = -3e38f, l0 = 0.f, l1 = 0.f;

    const int r0 = w * 16 + gid;    // first q row of this thread within tile

    for (int t = 0; t < 32; t++) {
        const int sbf = (t < 16) ? bf0 : bfi;
        const int k0 = (t & 15) * 64;

        #pragma unroll
        for (int i = 0; i < 4; i++) {
            int idx = tid + i * 128;
            int r = idx >> 3, c = (idx & 7) * 8;
            size_t base = (size_t)(sbf * SEQ + k0 + r) * D_MODEL + h * HDIM + c;
            *reinterpret_cast<uint4*>(&Ks[r][c]) = *reinterpret_cast<const uint4*>(g_k + base);
            *reinterpret_cast<uint4*>(&Vs[r][c]) = *reinterpret_cast<const uint4*>(g_v + base);
        }
        __syncthreads();

        // S = Q_scaled @ K^T : 16x64 per warp
        float sacc[8][4];
        #pragma unroll
        for (int nt = 0; nt < 8; nt++)
            #pragma unroll
            for (int i = 0; i < 4; i++) sacc[nt][i] = 0.f;

        #pragma unroll
        for (int kk = 0; kk < 64; kk += 16) {
            uint32_t aq[4];
            aq[0] = *reinterpret_cast<const uint32_t*>(&Qs[r0][kk + 2 * tig]);
            aq[1] = *reinterpret_cast<const uint32_t*>(&Qs[r0 + 8][kk + 2 * tig]);
            aq[2] = *reinterpret_cast<const uint32_t*>(&Qs[r0][kk + 2 * tig + 8]);
            aq[3] = *reinterpret_cast<const uint32_t*>(&Qs[r0 + 8][kk + 2 * tig + 8]);
            #pragma unroll
            for (int nt = 0; nt < 8; nt++) {
                uint32_t bk[2];
                bk[0] = *reinterpret_cast<const uint32_t*>(&Ks[nt * 8 + gid][kk + 2 * tig]);
                bk[1] = *reinterpret_cast<const uint32_t*>(&Ks[nt * 8 + gid][kk + 2 * tig + 8]);
                mma_bf16(sacc[nt], aq, bk);
            }
        }

        // Online softmax (rows r0, r0+8)
        float mx0 = -3e38f, mx1 = -3e38f;
        #pragma unroll
        for (int nt = 0; nt < 8; nt++) {
            mx0 = fmaxf(mx0, fmaxf(sacc[nt][0], sacc[nt][1]));
            mx1 = fmaxf(mx1, fmaxf(sacc[nt][2], sacc[nt][3]));
        }
        mx0 = fmaxf(mx0, __shfl_xor_sync(0xffffffffu, mx0, 1));
        mx0 = fmaxf(mx0, __shfl_xor_sync(0xffffffffu, mx0, 2));
        mx1 = fmaxf(mx1, __shfl_xor_sync(0xffffffffu, mx1, 1));
        mx1 = fmaxf(mx1, __shfl_xor_sync(0xffffffffu, mx1, 2));

        float mn0 = fmaxf(m0, mx0), mn1 = fmaxf(m1, mx1);
        float a0 = __expf(m0 - mn0), a1 = __expf(m1 - mn1);
        float s0 = 0.f, s1 = 0.f;
        #pragma unroll
        for (int nt = 0; nt < 8; nt++) {
            float p0 = __expf(sacc[nt][0] - mn0), p1 = __expf(sacc[nt][1] - mn0);
            float p2 = __expf(sacc[nt][2] - mn1), p3 = __expf(sacc[nt][3] - mn1);
            s0 += p0 + p1; s1 += p2 + p3;
            sacc[nt][0] = p0; sacc[nt][1] = p1; sacc[nt][2] = p2; sacc[nt][3] = p3;
        }
        s0 += __shfl_xor_sync(0xffffffffu, s0, 1);
        s0 += __shfl_xor_sync(0xffffffffu, s0, 2);
        s1 += __shfl_xor_sync(0xffffffffu, s1, 1);
        s1 += __shfl_xor_sync(0xffffffffu, s1, 2);
        l0 = l0 * a0 + s0; l1 = l1 * a1 + s1;
        m0 = mn0; m1 = mn1;

        #pragma unroll
        for (int nt = 0; nt < 8; nt++) {
            oacc[nt][0] *= a0; oacc[nt][1] *= a0;
            oacc[nt][2] *= a1; oacc[nt][3] *= a1;
        }

        // O += P @ V : P from registers (acc->A-frag identity), V^T via ldmatrix.trans
        #pragma unroll
        for (int kj = 0; kj < 4; kj++) {
            uint32_t ap[4];
            ap[0] = packbf(sacc[2 * kj][0],     sacc[2 * kj][1]);
            ap[1] = packbf(sacc[2 * kj][2],     sacc[2 * kj][3]);
            ap[2] = packbf(sacc[2 * kj + 1][0], sacc[2 * kj + 1][1]);
            ap[3] = packbf(sacc[2 * kj + 1][2], sacc[2 * kj + 1][3]);
            #pragma unroll
            for (int dp = 0; dp < 4; dp++) {
                int vrow = kj * 16 + ((lane >> 3) & 1) * 8 + (lane & 7);
                int vcol = dp * 16 + ((lane >> 4) & 1) * 8;
                uint32_t addr = (uint32_t)__cvta_generic_to_shared(&Vs[vrow][vcol]);
                uint32_t b0, b1, b2, b3;
                asm volatile(
                    "ldmatrix.sync.aligned.m8n8.x4.trans.shared.b16 {%0,%1,%2,%3}, [%4];\n"
                    : "=r"(b0), "=r"(b1), "=r"(b2), "=r"(b3) : "r"(addr));
                uint32_t bb0[2] = {b0, b1};
                uint32_t bb1[2] = {b2, b3};
                mma_bf16(oacc[2 * dp],     ap, bb0);
                mma_bf16(oacc[2 * dp + 1], ap, bb1);
            }
        }
        __syncthreads();
    }

    const float inv0 = 1.f / l0, inv1 = 1.f / l1;
    #pragma unroll
    for (int nt = 0; nt < 8; nt++) {
        int dcol = h * HDIM + nt * 8 + 2 * tig;
        size_t b0 = (size_t)(bfi * SEQ + qt * 64 + r0) * D_MODEL + dcol;
        size_t b1 = b0 + 8 * (size_t)D_MODEL;
        *reinterpret_cast<__nv_bfloat162*>(g_attn + b0) =
            __floats2bfloat162_rn(oacc[nt][0] * inv0, oacc[nt][1] * inv0);
        *reinterpret_cast<__nv_bfloat162*>(g_attn + b1) =
            __floats2bfloat162_rn(oacc[nt][2] * inv1, oacc[nt][3] * inv1);
    }
}

// ---------------------------------------------------------------------------

extern "C" void kernel_launch(void* const* d_in, const int* in_sizes, int n_in,
                              void* d_out, int out_size)
{
    const float* hs = (const float*)d_in[0];
    const float* Wq = (const float*)d_in[1];
    const float* Wk = (const float*)d_in[2];
    const float* Wv = (const float*)d_in[3];
    const float* Wo = (const float*)d_in[4];
    const float* bq = (const float*)d_in[5];
    const float* bk = (const float*)d_in[6];
    const float* bv = (const float*)d_in[7];
    const float* bo = (const float*)d_in[8];
    float* out = (float*)d_out;

    void *qp, *kp, *vp, *ap;
    cudaGetSymbolAddress(&qp, g_q);
    cudaGetSymbolAddress(&kp, g_k);
    cudaGetSymbolAddress(&vp, g_v);
    cudaGetSymbolAddress(&ap, g_attn);

    dim3 blk(256), grd(D_MODEL / 128, M_TOT / 128);
    gemm_kernel<false, true, false><<<grd, blk>>>(hs, Wq, bq, nullptr, qp, M_TOT, D_MODEL, D_MODEL);
    gemm_kernel<false, true, false><<<grd, blk>>>(hs, Wk, bk, nullptr, kp, M_TOT, D_MODEL, D_MODEL);
    gemm_kernel<false, true, false><<<grd, blk>>>(hs, Wv, bv, nullptr, vp, M_TOT, D_MODEL, D_MODEL);

    attn_kernel<<<dim3(SEQ / 64, N_HEADS, N_BF), 128>>>();

    gemm_kernel<true, false, true><<<grd, blk>>>(ap, Wo, bo, hs, out, M_TOT, D_MODEL, D_MODEL);
}

// round 5
// speedup vs baseline: 2.4149x; 2.4149x over previous
#include <cuda_runtime.h>
#include <cuda_bf16.h>
#include <cstdint>

#define D_MODEL 1280
#define SEQ     1024
#define N_BF    8
#define N_FR    4
#define N_HEADS 20
#define HDIM    64
#define M_TOT   (N_BF*SEQ)   // 8192

// Scratch (allocation-free rule: device globals). All bf16.
__device__ __nv_bfloat16 g_hs[(size_t)M_TOT * D_MODEL];
__device__ __nv_bfloat16 g_wq[(size_t)D_MODEL * D_MODEL];
__device__ __nv_bfloat16 g_wk[(size_t)D_MODEL * D_MODEL];
__device__ __nv_bfloat16 g_wv[(size_t)D_MODEL * D_MODEL];
__device__ __nv_bfloat16 g_wo[(size_t)D_MODEL * D_MODEL];
__device__ __nv_bfloat16 g_q[(size_t)M_TOT * D_MODEL];
__device__ __nv_bfloat16 g_k[(size_t)M_TOT * D_MODEL];
__device__ __nv_bfloat16 g_v[(size_t)M_TOT * D_MODEL];
__device__ __nv_bfloat16 g_attn[(size_t)M_TOT * D_MODEL];

__device__ __forceinline__ uint32_t packbf(float lo, float hi) {
    __nv_bfloat162 h = __floats2bfloat162_rn(lo, hi);
    return *reinterpret_cast<uint32_t*>(&h);
}

__device__ __forceinline__ void mma_bf16(float d[4], const uint32_t a[4], const uint32_t b[2]) {
    asm volatile(
        "mma.sync.aligned.m16n8k16.row.col.f32.bf16.bf16.f32 "
        "{%0,%1,%2,%3}, {%4,%5,%6,%7}, {%8,%9}, {%0,%1,%2,%3};\n"
        : "+f"(d[0]), "+f"(d[1]), "+f"(d[2]), "+f"(d[3])
        : "r"(a[0]), "r"(a[1]), "r"(a[2]), "r"(a[3]),
          "r"(b[0]), "r"(b[1]));
}

__device__ __forceinline__ void ldm_x4(uint32_t& r0, uint32_t& r1, uint32_t& r2, uint32_t& r3,
                                       const void* p) {
    uint32_t a = (uint32_t)__cvta_generic_to_shared(p);
    asm volatile("ldmatrix.sync.aligned.m8n8.x4.shared.b16 {%0,%1,%2,%3}, [%4];\n"
                 : "=r"(r0), "=r"(r1), "=r"(r2), "=r"(r3) : "r"(a));
}

__device__ __forceinline__ void ldm_x4_t(uint32_t& r0, uint32_t& r1, uint32_t& r2, uint32_t& r3,
                                         const void* p) {
    uint32_t a = (uint32_t)__cvta_generic_to_shared(p);
    asm volatile("ldmatrix.sync.aligned.m8n8.x4.trans.shared.b16 {%0,%1,%2,%3}, [%4];\n"
                 : "=r"(r0), "=r"(r1), "=r"(r2), "=r"(r3) : "r"(a));
}

__device__ __forceinline__ void cp16(void* smem, const void* gmem) {
    uint32_t s = (uint32_t)__cvta_generic_to_shared(smem);
    asm volatile("cp.async.cg.shared.global [%0], [%1], 16;\n" :: "r"(s), "l"(gmem));
}
__device__ __forceinline__ void cp_commit() { asm volatile("cp.async.commit_group;\n"); }
__device__ __forceinline__ void cp_wait0()  { asm volatile("cp.async.wait_group 0;\n"); }

// ---------------------------------------------------------------------------
// fp32 -> bf16 converter (vectorized, grid-strided not needed: exact grids)
// ---------------------------------------------------------------------------
__global__ void cvt_kernel(const float* __restrict__ in, __nv_bfloat16* __restrict__ out, int n)
{
    int i = (blockIdx.x * blockDim.x + threadIdx.x) * 4;
    if (i >= n) return;
    float4 v = *reinterpret_cast<const float4*>(in + i);
    __nv_bfloat162 lo = __floats2bfloat162_rn(v.x, v.y);
    __nv_bfloat162 hi = __floats2bfloat162_rn(v.z, v.w);
    uint2 o = make_uint2(*reinterpret_cast<uint32_t*>(&lo), *reinterpret_cast<uint32_t*>(&hi));
    *reinterpret_cast<uint2*>(out + i) = o;
}

// ---------------------------------------------------------------------------
// C[M,N] = A[M,K] @ W[K,N] + bias (+ residual). All-bf16 inputs, cp.async
// double-buffered, ldmatrix fragments. 128x128x32 tiles, 256 thr (2x4 warps).
// ---------------------------------------------------------------------------
template<bool OUT_BF16, bool ADD_RES>
__global__ __launch_bounds__(256, 2)
void gemm_kernel(const __nv_bfloat16* __restrict__ A, const __nv_bfloat16* __restrict__ W,
                 const float* __restrict__ bias, const float* __restrict__ res,
                 void* __restrict__ Cp, int M, int N, int K)
{
    __shared__ __nv_bfloat16 As[2][128][40];    // [m][k], row stride 80B = 20 banks
    __shared__ __nv_bfloat16 Bs[2][32][136];    // [k][n], row stride 272B = 4 banks

    const int bm = blockIdx.y, bn = blockIdx.x;
    const int tid = threadIdx.x;
    const int warp = tid >> 5, lane = tid & 31;
    const int wm = warp >> 2, wn = warp & 3;     // 2x4 warp grid, each 64x32
    const int gid = lane >> 2, tig = lane & 3;
    const int l15 = lane & 15, lhi = (lane >> 4) << 3;

    float acc[4][4][4];
    #pragma unroll
    for (int mt = 0; mt < 4; mt++)
        #pragma unroll
        for (int nt = 0; nt < 4; nt++)
            #pragma unroll
            for (int i = 0; i < 4; i++) acc[mt][nt][i] = 0.f;

    auto stage = [&](int buf, int kt) {
        #pragma unroll
        for (int i = 0; i < 2; i++) {       // A: 128x32 = 512 8-elem chunks
            int idx = tid + i * 256;
            int r = idx >> 2, c = (idx & 3) * 8;
            cp16(&As[buf][r][c], A + (size_t)(bm * 128 + r) * K + kt + c);
        }
        #pragma unroll
        for (int i = 0; i < 2; i++) {       // B: 32x128 = 512 8-elem chunks
            int idx = tid + i * 256;
            int r = idx >> 4, c = (idx & 15) * 8;
            cp16(&Bs[buf][r][c], W + (size_t)(kt + r) * N + bn * 128 + c);
        }
        cp_commit();
    };

    int buf = 0;
    stage(0, 0);

    for (int kt = 0; kt < K; kt += 32) {
        cp_wait0();
        __syncthreads();
        if (kt + 32 < K) stage(buf ^ 1, kt + 32);

        #pragma unroll
        for (int kk = 0; kk < 32; kk += 16) {
            uint32_t aA[4][4];
            #pragma unroll
            for (int mt = 0; mt < 4; mt++)
                ldm_x4(aA[mt][0], aA[mt][1], aA[mt][2], aA[mt][3],
                       &As[buf][wm * 64 + mt * 16 + l15][kk + lhi]);
            uint32_t bB[4][2];
            #pragma unroll
            for (int nh = 0; nh < 2; nh++) {
                uint32_t t0, t1, t2, t3;
                ldm_x4_t(t0, t1, t2, t3,
                         &Bs[buf][kk + l15][wn * 32 + nh * 16 + lhi]);
                bB[2 * nh][0] = t0; bB[2 * nh][1] = t1;
                bB[2 * nh + 1][0] = t2; bB[2 * nh + 1][1] = t3;
            }
            #pragma unroll
            for (int mt = 0; mt < 4; mt++)
                #pragma unroll
                for (int nt = 0; nt < 4; nt++)
                    mma_bf16(acc[mt][nt], aA[mt], bB[nt]);
        }
        buf ^= 1;
    }

    // Epilogue
    #pragma unroll
    for (int mt = 0; mt < 4; mt++) {
        int row = bm * 128 + wm * 64 + mt * 16 + gid;
        #pragma unroll
        for (int nt = 0; nt < 4; nt++) {
            int col = bn * 128 + wn * 32 + nt * 8 + 2 * tig;
            float b0 = bias[col], b1 = bias[col + 1];
            size_t i0 = (size_t)row * N + col;
            size_t i1 = i0 + 8 * (size_t)N;
            float v0 = acc[mt][nt][0] + b0, v1 = acc[mt][nt][1] + b1;
            float v2 = acc[mt][nt][2] + b0, v3 = acc[mt][nt][3] + b1;
            if (OUT_BF16) {
                __nv_bfloat16* C = (__nv_bfloat16*)Cp;
                *reinterpret_cast<__nv_bfloat162*>(C + i0) = __floats2bfloat162_rn(v0, v1);
                *reinterpret_cast<__nv_bfloat162*>(C + i1) = __floats2bfloat162_rn(v2, v3);
            } else {
                float* C = (float*)Cp;
                if (ADD_RES) { v0 += res[i0]; v1 += res[i0 + 1]; v2 += res[i1]; v3 += res[i1 + 1]; }
                C[i0] = v0; C[i0 + 1] = v1; C[i1] = v2; C[i1 + 1] = v3;
            }
        }
    }
}

// ---------------------------------------------------------------------------
// Flash attention over 2S keys. bf16 m16n8k16. Q fragments register-resident,
// K fragments via ldmatrix.x4, P in registers, V^T via ldmatrix.x4.trans,
// K/V staged via cp.async double buffer. Block = (qtile 64, head, bf), 4 warps.
// ---------------------------------------------------------------------------
__global__ __launch_bounds__(128)
void attn_kernel()
{
    __shared__ __nv_bfloat16 Qs[64][72];
    __shared__ __nv_bfloat16 Ks[2][64][72];
    __shared__ __nv_bfloat16 Vs[2][64][72];

    const int qt = blockIdx.x, h = blockIdx.y, bfi = blockIdx.z;
    const int bf0 = bfi & ~(N_FR - 1);
    const int tid = threadIdx.x;
    const int w = tid >> 5, lane = tid & 31;
    const int gid = lane >> 2, tig = lane & 3;
    const int l15 = lane & 15, lhi = (lane >> 4) << 3;

    // Stage Q tile, pre-scaled by 1/sqrt(64) = 0.125 (exact in bf16)
    {
        const __nv_bfloat162 sc = __floats2bfloat162_rn(0.125f, 0.125f);
        #pragma unroll
        for (int i = 0; i < 4; i++) {
            int idx = tid + i * 128;
            int r = idx >> 3, c = (idx & 7) * 8;
            const __nv_bfloat16* p = g_q + (size_t)(bfi * SEQ + qt * 64 + r) * D_MODEL + h * HDIM + c;
            uint4 v = *reinterpret_cast<const uint4*>(p);
            __nv_bfloat162* pv = reinterpret_cast<__nv_bfloat162*>(&v);
            #pragma unroll
            for (int j = 0; j < 4; j++) pv[j] = __hmul2(pv[j], sc);
            *reinterpret_cast<uint4*>(&Qs[r][c]) = v;
        }
    }

    auto stageKV = [&](int buf, int t) {
        const int sbf = (t < 16) ? bf0 : bfi;
        const int k0 = (t & 15) * 64;
        #pragma unroll
        for (int i = 0; i < 4; i++) {
            int idx = tid + i * 128;
            int r = idx >> 3, c = (idx & 7) * 8;
            size_t base = (size_t)(sbf * SEQ + k0 + r) * D_MODEL + h * HDIM + c;
            cp16(&Ks[buf][r][c], g_k + base);
            cp16(&Vs[buf][r][c], g_v + base);
        }
        cp_commit();
    };

    stageKV(0, 0);
    __syncthreads();            // Qs visible to all warps

    // Hoist Q fragments to registers (16 regs)
    uint32_t qf[4][4];
    #pragma unroll
    for (int kj = 0; kj < 4; kj++)
        ldm_x4(qf[kj][0], qf[kj][1], qf[kj][2], qf[kj][3],
               &Qs[w * 16 + l15][kj * 16 + lhi]);

    float oacc[8][4];
    #pragma unroll
    for (int nt = 0; nt < 8; nt++)
        #pragma unroll
        for (int i = 0; i < 4; i++) oacc[nt][i] = 0.f;
    float m0 = -3e38f, m1 = -3e38f, l0 = 0.f, l1 = 0.f;

    int buf = 0;
    for (int t = 0; t < 32; t++) {
        cp_wait0();
        __syncthreads();
        if (t + 1 < 32) stageKV(buf ^ 1, t + 1);

        // S = Q_scaled @ K^T : 16x64 per warp
        float sacc[8][4];
        #pragma unroll
        for (int nt = 0; nt < 8; nt++)
            #pragma unroll
            for (int i = 0; i < 4; i++) sacc[nt][i] = 0.f;

        #pragma unroll
        for (int ntp = 0; ntp < 4; ntp++) {
            #pragma unroll
            for (int kj = 0; kj < 4; kj++) {
                uint32_t t0, t1, t2, t3;
                ldm_x4(t0, t1, t2, t3, &Ks[buf][ntp * 16 + l15][kj * 16 + lhi]);
                uint32_t be[2] = {t0, t2};   // n-lo 8 rows
                uint32_t bo[2] = {t1, t3};   // n-hi 8 rows
                mma_bf16(sacc[2 * ntp],     qf[kj], be);
                mma_bf16(sacc[2 * ntp + 1], qf[kj], bo);
            }
        }

        // Online softmax (rows r0, r0+8)
        float mx0 = -3e38f, mx1 = -3e38f;
        #pragma unroll
        for (int nt = 0; nt < 8; nt++) {
            mx0 = fmaxf(mx0, fmaxf(sacc[nt][0], sacc[nt][1]));
            mx1 = fmaxf(mx1, fmaxf(sacc[nt][2], sacc[nt][3]));
        }
        mx0 = fmaxf(mx0, __shfl_xor_sync(0xffffffffu, mx0, 1));
        mx0 = fmaxf(mx0, __shfl_xor_sync(0xffffffffu, mx0, 2));
        mx1 = fmaxf(mx1, __shfl_xor_sync(0xffffffffu, mx1, 1));
        mx1 = fmaxf(mx1, __shfl_xor_sync(0xffffffffu, mx1, 2));

        float mn0 = fmaxf(m0, mx0), mn1 = fmaxf(m1, mx1);
        float a0 = __expf(m0 - mn0), a1 = __expf(m1 - mn1);
        float s0 = 0.f, s1 = 0.f;
        #pragma unroll
        for (int nt = 0; nt < 8; nt++) {
            float p0 = __expf(sacc[nt][0] - mn0), p1 = __expf(sacc[nt][1] - mn0);
            float p2 = __expf(sacc[nt][2] - mn1), p3 = __expf(sacc[nt][3] - mn1);
            s0 += p0 + p1; s1 += p2 + p3;
            sacc[nt][0] = p0; sacc[nt][1] = p1; sacc[nt][2] = p2; sacc[nt][3] = p3;
        }
        s0 += __shfl_xor_sync(0xffffffffu, s0, 1);
        s0 += __shfl_xor_sync(0xffffffffu, s0, 2);
        s1 += __shfl_xor_sync(0xffffffffu, s1, 1);
        s1 += __shfl_xor_sync(0xffffffffu, s1, 2);
        l0 = l0 * a0 + s0; l1 = l1 * a1 + s1;
        m0 = mn0; m1 = mn1;

        #pragma unroll
        for (int nt = 0; nt < 8; nt++) {
            oacc[nt][0] *= a0; oacc[nt][1] *= a0;
            oacc[nt][2] *= a1; oacc[nt][3] *= a1;
        }

        // O += P @ V : P from registers, V^T via ldmatrix.x4.trans
        #pragma unroll
        for (int kj = 0; kj < 4; kj++) {
            uint32_t ap[4];
            ap[0] = packbf(sacc[2 * kj][0],     sacc[2 * kj][1]);
            ap[1] = packbf(sacc[2 * kj][2],     sacc[2 * kj][3]);
            ap[2] = packbf(sacc[2 * kj + 1][0], sacc[2 * kj + 1][1]);
            ap[3] = packbf(sacc[2 * kj + 1][2], sacc[2 * kj + 1][3]);
            int vrow = kj * 16 + ((lane >> 3) & 1) * 8 + (lane & 7);
            #pragma unroll
            for (int dp = 0; dp < 4; dp++) {
                int vcol = dp * 16 + ((lane >> 4) & 1) * 8;
                uint32_t b0, b1, b2, b3;
                ldm_x4_t(b0, b1, b2, b3, &Vs[buf][vrow][vcol]);
                uint32_t bb0[2] = {b0, b1};
                uint32_t bb1[2] = {b2, b3};
                mma_bf16(oacc[2 * dp],     ap, bb0);
                mma_bf16(oacc[2 * dp + 1], ap, bb1);
            }
        }
        buf ^= 1;
    }

    const int r0 = w * 16 + gid;
    const float inv0 = 1.f / l0, inv1 = 1.f / l1;
    #pragma unroll
    for (int nt = 0; nt < 8; nt++) {
        int dcol = h * HDIM + nt * 8 + 2 * tig;
        size_t b0 = (size_t)(bfi * SEQ + qt * 64 + r0) * D_MODEL + dcol;
        size_t b1 = b0 + 8 * (size_t)D_MODEL;
        *reinterpret_cast<__nv_bfloat162*>(g_attn + b0) =
            __floats2bfloat162_rn(oacc[nt][0] * inv0, oacc[nt][1] * inv0);
        *reinterpret_cast<__nv_bfloat162*>(g_attn + b1) =
            __floats2bfloat162_rn(oacc[nt][2] * inv1, oacc[nt][3] * inv1);
    }
}

// ---------------------------------------------------------------------------

extern "C" void kernel_launch(void* const* d_in, const int* in_sizes, int n_in,
                              void* d_out, int out_size)
{
    const float* hs = (const float*)d_in[0];
    const float* Wq = (const float*)d_in[1];
    const float* Wk = (const float*)d_in[2];
    const float* Wv = (const float*)d_in[3];
    const float* Wo = (const float*)d_in[4];
    const float* bq = (const float*)d_in[5];
    const float* bk = (const float*)d_in[6];
    const float* bv = (const float*)d_in[7];
    const float* bo = (const float*)d_in[8];
    float* out = (float*)d_out;

    __nv_bfloat16 *hsb, *wqb, *wkb, *wvb, *wob, *qp, *kp, *vp, *ap;
    cudaGetSymbolAddress((void**)&hsb, g_hs);
    cudaGetSymbolAddress((void**)&wqb, g_wq);
    cudaGetSymbolAddress((void**)&wkb, g_wk);
    cudaGetSymbolAddress((void**)&wvb, g_wv);
    cudaGetSymbolAddress((void**)&wob, g_wo);
    cudaGetSymbolAddress((void**)&qp, g_q);
    cudaGetSymbolAddress((void**)&kp, g_k);
    cudaGetSymbolAddress((void**)&vp, g_v);
    cudaGetSymbolAddress((void**)&ap, g_attn);

    const int n_hs = M_TOT * D_MODEL, n_w = D_MODEL * D_MODEL;
    cvt_kernel<<<n_hs / 4 / 256, 256>>>(hs, hsb, n_hs);
    cvt_kernel<<<n_w / 4 / 256, 256>>>(Wq, wqb, n_w);
    cvt_kernel<<<n_w / 4 / 256, 256>>>(Wk, wkb, n_w);
    cvt_kernel<<<n_w / 4 / 256, 256>>>(Wv, wvb, n_w);
    cvt_kernel<<<n_w / 4 / 256, 256>>>(Wo, wob, n_w);

    dim3 blk(256), grd(D_MODEL / 128, M_TOT / 128);
    gemm_kernel<true, false><<<grd, blk>>>(hsb, wqb, bq, nullptr, qp, M_TOT, D_MODEL, D_MODEL);
    gemm_kernel<true, false><<<grd, blk>>>(hsb, wkb, bk, nullptr, kp, M_TOT, D_MODEL, D_MODEL);
    gemm_kernel<true, false><<<grd, blk>>>(hsb, wvb, bv, nullptr, vp, M_TOT, D_MODEL, D_MODEL);

    attn_kernel<<<dim3(SEQ / 64, N_HEADS, N_BF), 128>>>();

    gemm_kernel<false, true><<<grd, blk>>>(ap, wob, bo, hs, out, M_TOT, D_MODEL, D_MODEL);
}

// round 7
// speedup vs baseline: 2.6019x; 1.0774x over previous
#include <cuda_runtime.h>
#include <cuda_bf16.h>
#include <cstdint>

#define D_MODEL 1280
#define SEQ     1024
#define N_BF    8
#define N_FR    4
#define N_HEADS 20
#define HDIM    64
#define M_TOT   (N_BF*SEQ)   // 8192

// Scratch (allocation-free rule: device globals). All bf16.
__device__ __nv_bfloat16 g_hs[(size_t)M_TOT * D_MODEL];
__device__ __nv_bfloat16 g_wq[(size_t)D_MODEL * D_MODEL];
__device__ __nv_bfloat16 g_wk[(size_t)D_MODEL * D_MODEL];
__device__ __nv_bfloat16 g_wv[(size_t)D_MODEL * D_MODEL];
__device__ __nv_bfloat16 g_wo[(size_t)D_MODEL * D_MODEL];
__device__ __nv_bfloat16 g_q[(size_t)M_TOT * D_MODEL];
__device__ __nv_bfloat16 g_k[(size_t)M_TOT * D_MODEL];
__device__ __nv_bfloat16 g_v[(size_t)M_TOT * D_MODEL];
__device__ __nv_bfloat16 g_attn[(size_t)M_TOT * D_MODEL];

__device__ __forceinline__ uint32_t packbf(float lo, float hi) {
    __nv_bfloat162 h = __floats2bfloat162_rn(lo, hi);
    return *reinterpret_cast<uint32_t*>(&h);
}

__device__ __forceinline__ void mma_bf16(float d[4], const uint32_t a[4], const uint32_t b[2]) {
    asm volatile(
        "mma.sync.aligned.m16n8k16.row.col.f32.bf16.bf16.f32 "
        "{%0,%1,%2,%3}, {%4,%5,%6,%7}, {%8,%9}, {%0,%1,%2,%3};\n"
        : "+f"(d[0]), "+f"(d[1]), "+f"(d[2]), "+f"(d[3])
        : "r"(a[0]), "r"(a[1]), "r"(a[2]), "r"(a[3]),
          "r"(b[0]), "r"(b[1]));
}

__device__ __forceinline__ void ldm_x4(uint32_t& r0, uint32_t& r1, uint32_t& r2, uint32_t& r3,
                                       const void* p) {
    uint32_t a = (uint32_t)__cvta_generic_to_shared(p);
    asm volatile("ldmatrix.sync.aligned.m8n8.x4.shared.b16 {%0,%1,%2,%3}, [%4];\n"
                 : "=r"(r0), "=r"(r1), "=r"(r2), "=r"(r3) : "r"(a));
}

__device__ __forceinline__ void ldm_x4_t(uint32_t& r0, uint32_t& r1, uint32_t& r2, uint32_t& r3,
                                         const void* p) {
    uint32_t a = (uint32_t)__cvta_generic_to_shared(p);
    asm volatile("ldmatrix.sync.aligned.m8n8.x4.trans.shared.b16 {%0,%1,%2,%3}, [%4];\n"
                 : "=r"(r0), "=r"(r1), "=r"(r2), "=r"(r3) : "r"(a));
}

__device__ __forceinline__ void cp16(void* smem, const void* gmem) {
    uint32_t s = (uint32_t)__cvta_generic_to_shared(smem);
    asm volatile("cp.async.cg.shared.global [%0], [%1], 16;\n" :: "r"(s), "l"(gmem));
}
__device__ __forceinline__ void cp_commit() { asm volatile("cp.async.commit_group;\n"); }
__device__ __forceinline__ void cp_wait0()  { asm volatile("cp.async.wait_group 0;\n"); }
__device__ __forceinline__ void cp_wait2()  { asm volatile("cp.async.wait_group 2;\n"); }

// ---------------------------------------------------------------------------
// fp32 -> bf16 converter
// ---------------------------------------------------------------------------
__global__ void cvt_kernel(const float* __restrict__ in, __nv_bfloat16* __restrict__ out, int n)
{
    int i = (blockIdx.x * blockDim.x + threadIdx.x) * 4;
    if (i >= n) return;
    float4 v = *reinterpret_cast<const float4*>(in + i);
    __nv_bfloat162 lo = __floats2bfloat162_rn(v.x, v.y);
    __nv_bfloat162 hi = __floats2bfloat162_rn(v.z, v.w);
    uint2 o = make_uint2(*reinterpret_cast<uint32_t*>(&lo), *reinterpret_cast<uint32_t*>(&hi));
    *reinterpret_cast<uint2*>(out + i) = o;
}

// Fused 4-weight converter (grid.z routes)
__global__ void cvt4_kernel(const float* __restrict__ s0, const float* __restrict__ s1,
                            const float* __restrict__ s2, const float* __restrict__ s3,
                            __nv_bfloat16* __restrict__ d0, __nv_bfloat16* __restrict__ d1,
                            __nv_bfloat16* __restrict__ d2, __nv_bfloat16* __restrict__ d3,
                            int n)
{
    const float* in = (blockIdx.z == 0) ? s0 : (blockIdx.z == 1) ? s1
                    : (blockIdx.z == 2) ? s2 : s3;
    __nv_bfloat16* out = (blockIdx.z == 0) ? d0 : (blockIdx.z == 1) ? d1
                       : (blockIdx.z == 2) ? d2 : d3;
    int i = (blockIdx.x * blockDim.x + threadIdx.x) * 4;
    if (i >= n) return;
    float4 v = *reinterpret_cast<const float4*>(in + i);
    __nv_bfloat162 lo = __floats2bfloat162_rn(v.x, v.y);
    __nv_bfloat162 hi = __floats2bfloat162_rn(v.z, v.w);
    uint2 o = make_uint2(*reinterpret_cast<uint32_t*>(&lo), *reinterpret_cast<uint32_t*>(&hi));
    *reinterpret_cast<uint2*>(out + i) = o;
}

// ---------------------------------------------------------------------------
// C[M,N] = A[M,K] @ W[K,N] + bias (+ residual). All-bf16 inputs.
// 4-stage cp.async pipeline (wait_group 2), ldmatrix fragments.
// 128x128x32 tiles, 256 thr (2x4 warps). grid.x routes among up to 3 weights.
// ---------------------------------------------------------------------------
#define GK_NSTG   (D_MODEL / 32)   // 40
#define GA_ELEMS  (128 * 40)       // per A buffer
#define GB_ELEMS  (32 * 136)       // per B buffer
#define G_SMEM    ((4 * GA_ELEMS + 4 * GB_ELEMS) * 2)   // 75776 B

template<bool OUT_BF16, bool ADD_RES>
__global__ __launch_bounds__(256, 2)
void gemm_kernel(const __nv_bfloat16* __restrict__ A,
                 const __nv_bfloat16* __restrict__ W0, const __nv_bfloat16* __restrict__ W1,
                 const __nv_bfloat16* __restrict__ W2,
                 const float* __restrict__ b0, const float* __restrict__ b1,
                 const float* __restrict__ b2,
                 void* __restrict__ o0, void* __restrict__ o1, void* __restrict__ o2,
                 const float* __restrict__ res, int M, int N, int K)
{
    extern __shared__ __align__(16) char smem[];
    __nv_bfloat16* Abase = reinterpret_cast<__nv_bfloat16*>(smem);
    __nv_bfloat16* Bbase = Abase + 4 * GA_ELEMS;

    const int bm = blockIdx.y;
    const int which = blockIdx.x / 10, bn = blockIdx.x % 10;
    const __nv_bfloat16* W = (which == 0) ? W0 : (which == 1) ? W1 : W2;
    const float* bias = (which == 0) ? b0 : (which == 1) ? b1 : b2;
    void* outp = (which == 0) ? o0 : (which == 1) ? o1 : o2;

    const int tid = threadIdx.x;
    const int warp = tid >> 5, lane = tid & 31;
    const int wm = warp >> 2, wn = warp & 3;     // 2x4 warp grid, each 64x32
    const int gid = lane >> 2, tig = lane & 3;
    const int l15 = lane & 15, lhi = (lane >> 4) << 3;

    float acc[4][4][4];
    #pragma unroll
    for (int mt = 0; mt < 4; mt++)
        #pragma unroll
        for (int nt = 0; nt < 4; nt++)
            #pragma unroll
            for (int i = 0; i < 4; i++) acc[mt][nt][i] = 0.f;

    auto stage = [&](int s) {
        const int buf = s & 3;
        const int kt = s * 32;
        __nv_bfloat16* As = Abase + buf * GA_ELEMS;     // [128][40]
        __nv_bfloat16* Bs = Bbase + buf * GB_ELEMS;     // [32][136]
        #pragma unroll
        for (int i = 0; i < 2; i++) {       // A: 128x32 = 512 8-elem chunks
            int idx = tid + i * 256;
            int r = idx >> 2, c = (idx & 3) * 8;
            cp16(As + r * 40 + c, A + (size_t)(bm * 128 + r) * K + kt + c);
        }
        #pragma unroll
        for (int i = 0; i < 2; i++) {       // B: 32x128 = 512 8-elem chunks
            int idx = tid + i * 256;
            int r = idx >> 4, c = (idx & 15) * 8;
            cp16(Bs + r * 136 + c, W + (size_t)(kt + r) * N + bn * 128 + c);
        }
        cp_commit();
    };

    stage(0); stage(1); stage(2);

    for (int s = 0; s < GK_NSTG; s++) {
        cp_wait2();                 // group s complete (s+1, s+2 may be in flight)
        __syncthreads();
        if (s + 3 < GK_NSTG) stage(s + 3);
        else cp_commit();           // keep per-thread group count constant

        const int buf = s & 3;
        const __nv_bfloat16* As = Abase + buf * GA_ELEMS;
        const __nv_bfloat16* Bs = Bbase + buf * GB_ELEMS;

        #pragma unroll
        for (int kk = 0; kk < 32; kk += 16) {
            uint32_t aA[4][4];
            #pragma unroll
            for (int mt = 0; mt < 4; mt++)
                ldm_x4(aA[mt][0], aA[mt][1], aA[mt][2], aA[mt][3],
                       As + (wm * 64 + mt * 16 + l15) * 40 + kk + lhi);
            uint32_t bB[4][2];
            #pragma unroll
            for (int nh = 0; nh < 2; nh++) {
                uint32_t t0, t1, t2, t3;
                ldm_x4_t(t0, t1, t2, t3,
                         Bs + (kk + l15) * 136 + wn * 32 + nh * 16 + lhi);
                bB[2 * nh][0] = t0; bB[2 * nh][1] = t1;
                bB[2 * nh + 1][0] = t2; bB[2 * nh + 1][1] = t3;
            }
            #pragma unroll
            for (int mt = 0; mt < 4; mt++)
                #pragma unroll
                for (int nt = 0; nt < 4; nt++)
                    mma_bf16(acc[mt][nt], aA[mt], bB[nt]);
        }
    }

    // Epilogue
    #pragma unroll
    for (int mt = 0; mt < 4; mt++) {
        int row = bm * 128 + wm * 64 + mt * 16 + gid;
        #pragma unroll
        for (int nt = 0; nt < 4; nt++) {
            int col = bn * 128 + wn * 32 + nt * 8 + 2 * tig;
            float bb0 = bias[col], bb1 = bias[col + 1];
            size_t i0 = (size_t)row * N + col;
            size_t i1 = i0 + 8 * (size_t)N;
            float v0 = acc[mt][nt][0] + bb0, v1 = acc[mt][nt][1] + bb1;
            float v2 = acc[mt][nt][2] + bb0, v3 = acc[mt][nt][3] + bb1;
            if (OUT_BF16) {
                __nv_bfloat16* C = (__nv_bfloat16*)outp;
                *reinterpret_cast<__nv_bfloat162*>(C + i0) = __floats2bfloat162_rn(v0, v1);
                *reinterpret_cast<__nv_bfloat162*>(C + i1) = __floats2bfloat162_rn(v2, v3);
            } else {
                float* C = (float*)outp;
                if (ADD_RES) { v0 += res[i0]; v1 += res[i0 + 1]; v2 += res[i1]; v3 += res[i1 + 1]; }
                C[i0] = v0; C[i0 + 1] = v1; C[i1] = v2; C[i1 + 1] = v3;
            }
        }
    }
}

// ---------------------------------------------------------------------------
// Flash attention over 2S keys (unchanged from round 5 best).
// ---------------------------------------------------------------------------
__global__ __launch_bounds__(128)
void attn_kernel()
{
    __shared__ __nv_bfloat16 Qs[64][72];
    __shared__ __nv_bfloat16 Ks[2][64][72];
    __shared__ __nv_bfloat16 Vs[2][64][72];

    const int qt = blockIdx.x, h = blockIdx.y, bfi = blockIdx.z;
    const int bf0 = bfi & ~(N_FR - 1);
    const int tid = threadIdx.x;
    const int w = tid >> 5, lane = tid & 31;
    const int gid = lane >> 2, tig = lane & 3;
    const int l15 = lane & 15, lhi = (lane >> 4) << 3;

    {
        const __nv_bfloat162 sc = __floats2bfloat162_rn(0.125f, 0.125f);
        #pragma unroll
        for (int i = 0; i < 4; i++) {
            int idx = tid + i * 128;
            int r = idx >> 3, c = (idx & 7) * 8;
            const __nv_bfloat16* p = g_q + (size_t)(bfi * SEQ + qt * 64 + r) * D_MODEL + h * HDIM + c;
            uint4 v = *reinterpret_cast<const uint4*>(p);
            __nv_bfloat162* pv = reinterpret_cast<__nv_bfloat162*>(&v);
            #pragma unroll
            for (int j = 0; j < 4; j++) pv[j] = __hmul2(pv[j], sc);
            *reinterpret_cast<uint4*>(&Qs[r][c]) = v;
        }
    }

    auto stageKV = [&](int buf, int t) {
        const int sbf = (t < 16) ? bf0 : bfi;
        const int k0 = (t & 15) * 64;
        #pragma unroll
        for (int i = 0; i < 4; i++) {
            int idx = tid + i * 128;
            int r = idx >> 3, c = (idx & 7) * 8;
            size_t base = (size_t)(sbf * SEQ + k0 + r) * D_MODEL + h * HDIM + c;
            cp16(&Ks[buf][r][c], g_k + base);
            cp16(&Vs[buf][r][c], g_v + base);
        }
        cp_commit();
    };

    stageKV(0, 0);
    __syncthreads();

    uint32_t qf[4][4];
    #pragma unroll
    for (int kj = 0; kj < 4; kj++)
        ldm_x4(qf[kj][0], qf[kj][1], qf[kj][2], qf[kj][3],
               &Qs[w * 16 + l15][kj * 16 + lhi]);

    float oacc[8][4];
    #pragma unroll
    for (int nt = 0; nt < 8; nt++)
        #pragma unroll
        for (int i = 0; i < 4; i++) oacc[nt][i] = 0.f;
    float m0 = -3e38f, m1 = -3e38f, l0 = 0.f, l1 = 0.f;

    int buf = 0;
    for (int t = 0; t < 32; t++) {
        cp_wait0();
        __syncthreads();
        if (t + 1 < 32) stageKV(buf ^ 1, t + 1);

        float sacc[8][4];
        #pragma unroll
        for (int nt = 0; nt < 8; nt++)
            #pragma unroll
            for (int i = 0; i < 4; i++) sacc[nt][i] = 0.f;

        #pragma unroll
        for (int ntp = 0; ntp < 4; ntp++) {
            #pragma unroll
            for (int kj = 0; kj < 4; kj++) {
                uint32_t t0, t1, t2, t3;
                ldm_x4(t0, t1, t2, t3, &Ks[buf][ntp * 16 + l15][kj * 16 + lhi]);
                uint32_t be[2] = {t0, t2};
                uint32_t bo[2] = {t1, t3};
                mma_bf16(sacc[2 * ntp],     qf[kj], be);
                mma_bf16(sacc[2 * ntp + 1], qf[kj], bo);
            }
        }

        float mx0 = -3e38f, mx1 = -3e38f;
        #pragma unroll
        for (int nt = 0; nt < 8; nt++) {
            mx0 = fmaxf(mx0, fmaxf(sacc[nt][0], sacc[nt][1]));
            mx1 = fmaxf(mx1, fmaxf(sacc[nt][2], sacc[nt][3]));
        }
        mx0 = fmaxf(mx0, __shfl_xor_sync(0xffffffffu, mx0, 1));
        mx0 = fmaxf(mx0, __shfl_xor_sync(0xffffffffu, mx0, 2));
        mx1 = fmaxf(mx1, __shfl_xor_sync(0xffffffffu, mx1, 1));
        mx1 = fmaxf(mx1, __shfl_xor_sync(0xffffffffu, mx1, 2));

        float mn0 = fmaxf(m0, mx0), mn1 = fmaxf(m1, mx1);
        float a0 = __expf(m0 - mn0), a1 = __expf(m1 - mn1);
        float s0 = 0.f, s1 = 0.f;
        #pragma unroll
        for (int nt = 0; nt < 8; nt++) {
            float p0 = __expf(sacc[nt][0] - mn0), p1 = __expf(sacc[nt][1] - mn0);
            float p2 = __expf(sacc[nt][2] - mn1), p3 = __expf(sacc[nt][3] - mn1);
            s0 += p0 + p1; s1 += p2 + p3;
            sacc[nt][0] = p0; sacc[nt][1] = p1; sacc[nt][2] = p2; sacc[nt][3] = p3;
        }
        s0 += __shfl_xor_sync(0xffffffffu, s0, 1);
        s0 += __shfl_xor_sync(0xffffffffu, s0, 2);
        s1 += __shfl_xor_sync(0xffffffffu, s1, 1);
        s1 += __shfl_xor_sync(0xffffffffu, s1, 2);
        l0 = l0 * a0 + s0; l1 = l1 * a1 + s1;
        m0 = mn0; m1 = mn1;

        #pragma unroll
        for (int nt = 0; nt < 8; nt++) {
            oacc[nt][0] *= a0; oacc[nt][1] *= a0;
            oacc[nt][2] *= a1; oacc[nt][3] *= a1;
        }

        #pragma unroll
        for (int kj = 0; kj < 4; kj++) {
            uint32_t ap[4];
            ap[0] = packbf(sacc[2 * kj][0],     sacc[2 * kj][1]);
            ap[1] = packbf(sacc[2 * kj][2],     sacc[2 * kj][3]);
            ap[2] = packbf(sacc[2 * kj + 1][0], sacc[2 * kj + 1][1]);
            ap[3] = packbf(sacc[2 * kj + 1][2], sacc[2 * kj + 1][3]);
            int vrow = kj * 16 + ((lane >> 3) & 1) * 8 + (lane & 7);
            #pragma unroll
            for (int dp = 0; dp < 4; dp++) {
                int vcol = dp * 16 + ((lane >> 4) & 1) * 8;
                uint32_t b0, b1, b2, b3;
                ldm_x4_t(b0, b1, b2, b3, &Vs[buf][vrow][vcol]);
                uint32_t bb0[2] = {b0, b1};
                uint32_t bb1[2] = {b2, b3};
                mma_bf16(oacc[2 * dp],     ap, bb0);
                mma_bf16(oacc[2 * dp + 1], ap, bb1);
            }
        }
        buf ^= 1;
    }

    const int r0 = w * 16 + gid;
    const float inv0 = 1.f / l0, inv1 = 1.f / l1;
    #pragma unroll
    for (int nt = 0; nt < 8; nt++) {
        int dcol = h * HDIM + nt * 8 + 2 * tig;
        size_t b0 = (size_t)(bfi * SEQ + qt * 64 + r0) * D_MODEL + dcol;
        size_t b1 = b0 + 8 * (size_t)D_MODEL;
        *reinterpret_cast<__nv_bfloat162*>(g_attn + b0) =
            __floats2bfloat162_rn(oacc[nt][0] * inv0, oacc[nt][1] * inv0);
        *reinterpret_cast<__nv_bfloat162*>(g_attn + b1) =
            __floats2bfloat162_rn(oacc[nt][2] * inv1, oacc[nt][3] * inv1);
    }
}

// ---------------------------------------------------------------------------

extern "C" void kernel_launch(void* const* d_in, const int* in_sizes, int n_in,
                              void* d_out, int out_size)
{
    const float* hs = (const float*)d_in[0];
    const float* Wq = (const float*)d_in[1];
    const float* Wk = (const float*)d_in[2];
    const float* Wv = (const float*)d_in[3];
    const float* Wo = (const float*)d_in[4];
    const float* bq = (const float*)d_in[5];
    const float* bk = (const float*)d_in[6];
    const float* bv = (const float*)d_in[7];
    const float* bo = (const float*)d_in[8];
    float* out = (float*)d_out;

    __nv_bfloat16 *hsb, *wqb, *wkb, *wvb, *wob, *qp, *kp, *vp, *ap;
    cudaGetSymbolAddress((void**)&hsb, g_hs);
    cudaGetSymbolAddress((void**)&wqb, g_wq);
    cudaGetSymbolAddress((void**)&wkb, g_wk);
    cudaGetSymbolAddress((void**)&wvb, g_wv);
    cudaGetSymbolAddress((void**)&wob, g_wo);
    cudaGetSymbolAddress((void**)&qp, g_q);
    cudaGetSymbolAddress((void**)&kp, g_k);
    cudaGetSymbolAddress((void**)&vp, g_v);
    cudaGetSymbolAddress((void**)&ap, g_attn);

    const int n_hs = M_TOT * D_MODEL, n_w = D_MODEL * D_MODEL;
    cvt_kernel<<<n_hs / 4 / 256, 256>>>(hs, hsb, n_hs);
    cvt4_kernel<<<dim3(n_w / 4 / 256, 1, 4), 256>>>(Wq, Wk, Wv, Wo, wqb, wkb, wvb, wob, n_w);

    cudaFuncSetAttribute((const void*)gemm_kernel<true, false>,
                         cudaFuncAttributeMaxDynamicSharedMemorySize, G_SMEM);
    cudaFuncSetAttribute((const void*)gemm_kernel<false, true>,
                         cudaFuncAttributeMaxDynamicSharedMemorySize, G_SMEM);

    // Fused QKV: grid.x = 30 (3 weights x 10 n-tiles)
    gemm_kernel<true, false><<<dim3(30, M_TOT / 128), 256, G_SMEM>>>(
        hsb, wqb, wkb, wvb, bq, bk, bv, qp, kp, vp, nullptr, M_TOT, D_MODEL, D_MODEL);

    attn_kernel<<<dim3(SEQ / 64, N_HEADS, N_BF), 128>>>();

    gemm_kernel<false, true><<<dim3(10, M_TOT / 128), 256, G_SMEM>>>(
        ap, wob, wob, wob, bo, bo, bo, out, out, out, hs, M_TOT, D_MODEL, D_MODEL);
}

// round 8
// speedup vs baseline: 2.6095x; 1.0029x over previous
#include <cuda_runtime.h>
#include <cuda_bf16.h>
#include <cstdint>

#define D_MODEL 1280
#define SEQ     1024
#define N_BF    8
#define N_FR    4
#define N_HEADS 20
#define HDIM    64
#define M_TOT   (N_BF*SEQ)   // 8192

// Scratch (allocation-free rule: device globals). All bf16.
__device__ __nv_bfloat16 g_hs[(size_t)M_TOT * D_MODEL];
__device__ __nv_bfloat16 g_wq[(size_t)D_MODEL * D_MODEL];
__device__ __nv_bfloat16 g_wk[(size_t)D_MODEL * D_MODEL];
__device__ __nv_bfloat16 g_wv[(size_t)D_MODEL * D_MODEL];
__device__ __nv_bfloat16 g_wo[(size_t)D_MODEL * D_MODEL];
__device__ __nv_bfloat16 g_q[(size_t)M_TOT * D_MODEL];
__device__ __nv_bfloat16 g_k[(size_t)M_TOT * D_MODEL];
__device__ __nv_bfloat16 g_v[(size_t)M_TOT * D_MODEL];
__device__ __nv_bfloat16 g_attn[(size_t)M_TOT * D_MODEL];

__device__ __forceinline__ uint32_t packbf(float lo, float hi) {
    __nv_bfloat162 h = __floats2bfloat162_rn(lo, hi);
    return *reinterpret_cast<uint32_t*>(&h);
}

__device__ __forceinline__ void mma_bf16(float d[4], const uint32_t a[4], const uint32_t b[2]) {
    asm volatile(
        "mma.sync.aligned.m16n8k16.row.col.f32.bf16.bf16.f32 "
        "{%0,%1,%2,%3}, {%4,%5,%6,%7}, {%8,%9}, {%0,%1,%2,%3};\n"
        : "+f"(d[0]), "+f"(d[1]), "+f"(d[2]), "+f"(d[3])
        : "r"(a[0]), "r"(a[1]), "r"(a[2]), "r"(a[3]),
          "r"(b[0]), "r"(b[1]));
}

__device__ __forceinline__ void ldm_x4(uint32_t& r0, uint32_t& r1, uint32_t& r2, uint32_t& r3,
                                       const void* p) {
    uint32_t a = (uint32_t)__cvta_generic_to_shared(p);
    asm volatile("ldmatrix.sync.aligned.m8n8.x4.shared.b16 {%0,%1,%2,%3}, [%4];\n"
                 : "=r"(r0), "=r"(r1), "=r"(r2), "=r"(r3) : "r"(a));
}

__device__ __forceinline__ void ldm_x4_t(uint32_t& r0, uint32_t& r1, uint32_t& r2, uint32_t& r3,
                                         const void* p) {
    uint32_t a = (uint32_t)__cvta_generic_to_shared(p);
    asm volatile("ldmatrix.sync.aligned.m8n8.x4.trans.shared.b16 {%0,%1,%2,%3}, [%4];\n"
                 : "=r"(r0), "=r"(r1), "=r"(r2), "=r"(r3) : "r"(a));
}

__device__ __forceinline__ void cp16(void* smem, const void* gmem) {
    uint32_t s = (uint32_t)__cvta_generic_to_shared(smem);
    asm volatile("cp.async.cg.shared.global [%0], [%1], 16;\n" :: "r"(s), "l"(gmem));
}
__device__ __forceinline__ void cp_commit() { asm volatile("cp.async.commit_group;\n"); }
__device__ __forceinline__ void cp_wait0()  { asm volatile("cp.async.wait_group 0;\n"); }
__device__ __forceinline__ void cp_wait2()  { asm volatile("cp.async.wait_group 2;\n"); }

// ---------------------------------------------------------------------------
// fp32 -> bf16 converter
// ---------------------------------------------------------------------------
__global__ void cvt_kernel(const float* __restrict__ in, __nv_bfloat16* __restrict__ out, int n)
{
    int i = (blockIdx.x * blockDim.x + threadIdx.x) * 4;
    if (i >= n) return;
    float4 v = *reinterpret_cast<const float4*>(in + i);
    __nv_bfloat162 lo = __floats2bfloat162_rn(v.x, v.y);
    __nv_bfloat162 hi = __floats2bfloat162_rn(v.z, v.w);
    uint2 o = make_uint2(*reinterpret_cast<uint32_t*>(&lo), *reinterpret_cast<uint32_t*>(&hi));
    *reinterpret_cast<uint2*>(out + i) = o;
}

// Fused 4-weight converter (grid.z routes)
__global__ void cvt4_kernel(const float* __restrict__ s0, const float* __restrict__ s1,
                            const float* __restrict__ s2, const float* __restrict__ s3,
                            __nv_bfloat16* __restrict__ d0, __nv_bfloat16* __restrict__ d1,
                            __nv_bfloat16* __restrict__ d2, __nv_bfloat16* __restrict__ d3,
                            int n)
{
    const float* in = (blockIdx.z == 0) ? s0 : (blockIdx.z == 1) ? s1
                    : (blockIdx.z == 2) ? s2 : s3;
    __nv_bfloat16* out = (blockIdx.z == 0) ? d0 : (blockIdx.z == 1) ? d1
                       : (blockIdx.z == 2) ? d2 : d3;
    int i = (blockIdx.x * blockDim.x + threadIdx.x) * 4;
    if (i >= n) return;
    float4 v = *reinterpret_cast<const float4*>(in + i);
    __nv_bfloat162 lo = __floats2bfloat162_rn(v.x, v.y);
    __nv_bfloat162 hi = __floats2bfloat162_rn(v.z, v.w);
    uint2 o = make_uint2(*reinterpret_cast<uint32_t*>(&lo), *reinterpret_cast<uint32_t*>(&hi));
    *reinterpret_cast<uint2*>(out + i) = o;
}

// ---------------------------------------------------------------------------
// C[M,N] = A[M,K] @ W[K,N] + bias (+ residual). All-bf16 inputs.
// 4-stage cp.async pipeline (wait_group 2), ldmatrix fragments.
// 128x128x32 tiles, 256 thr (2x4 warps). grid.x routes among up to 3 weights.
// (unchanged from round 7)
// ---------------------------------------------------------------------------
#define GK_NSTG   (D_MODEL / 32)   // 40
#define GA_ELEMS  (128 * 40)
#define GB_ELEMS  (32 * 136)
#define G_SMEM    ((4 * GA_ELEMS + 4 * GB_ELEMS) * 2)   // 75776 B

template<bool OUT_BF16, bool ADD_RES>
__global__ __launch_bounds__(256, 2)
void gemm_kernel(const __nv_bfloat16* __restrict__ A,
                 const __nv_bfloat16* __restrict__ W0, const __nv_bfloat16* __restrict__ W1,
                 const __nv_bfloat16* __restrict__ W2,
                 const float* __restrict__ b0, const float* __restrict__ b1,
                 const float* __restrict__ b2,
                 void* __restrict__ o0, void* __restrict__ o1, void* __restrict__ o2,
                 const float* __restrict__ res, int M, int N, int K)
{
    extern __shared__ __align__(16) char smem[];
    __nv_bfloat16* Abase = reinterpret_cast<__nv_bfloat16*>(smem);
    __nv_bfloat16* Bbase = Abase + 4 * GA_ELEMS;

    const int bm = blockIdx.y;
    const int which = blockIdx.x / 10, bn = blockIdx.x % 10;
    const __nv_bfloat16* W = (which == 0) ? W0 : (which == 1) ? W1 : W2;
    const float* bias = (which == 0) ? b0 : (which == 1) ? b1 : b2;
    void* outp = (which == 0) ? o0 : (which == 1) ? o1 : o2;

    const int tid = threadIdx.x;
    const int warp = tid >> 5, lane = tid & 31;
    const int wm = warp >> 2, wn = warp & 3;
    const int gid = lane >> 2, tig = lane & 3;
    const int l15 = lane & 15, lhi = (lane >> 4) << 3;

    float acc[4][4][4];
    #pragma unroll
    for (int mt = 0; mt < 4; mt++)
        #pragma unroll
        for (int nt = 0; nt < 4; nt++)
            #pragma unroll
            for (int i = 0; i < 4; i++) acc[mt][nt][i] = 0.f;

    auto stage = [&](int s) {
        const int buf = s & 3;
        const int kt = s * 32;
        __nv_bfloat16* As = Abase + buf * GA_ELEMS;
        __nv_bfloat16* Bs = Bbase + buf * GB_ELEMS;
        #pragma unroll
        for (int i = 0; i < 2; i++) {
            int idx = tid + i * 256;
            int r = idx >> 2, c = (idx & 3) * 8;
            cp16(As + r * 40 + c, A + (size_t)(bm * 128 + r) * K + kt + c);
        }
        #pragma unroll
        for (int i = 0; i < 2; i++) {
            int idx = tid + i * 256;
            int r = idx >> 4, c = (idx & 15) * 8;
            cp16(Bs + r * 136 + c, W + (size_t)(kt + r) * N + bn * 128 + c);
        }
        cp_commit();
    };

    stage(0); stage(1); stage(2);

    for (int s = 0; s < GK_NSTG; s++) {
        cp_wait2();
        __syncthreads();
        if (s + 3 < GK_NSTG) stage(s + 3);
        else cp_commit();

        const int buf = s & 3;
        const __nv_bfloat16* As = Abase + buf * GA_ELEMS;
        const __nv_bfloat16* Bs = Bbase + buf * GB_ELEMS;

        #pragma unroll
        for (int kk = 0; kk < 32; kk += 16) {
            uint32_t aA[4][4];
            #pragma unroll
            for (int mt = 0; mt < 4; mt++)
                ldm_x4(aA[mt][0], aA[mt][1], aA[mt][2], aA[mt][3],
                       As + (wm * 64 + mt * 16 + l15) * 40 + kk + lhi);
            uint32_t bB[4][2];
            #pragma unroll
            for (int nh = 0; nh < 2; nh++) {
                uint32_t t0, t1, t2, t3;
                ldm_x4_t(t0, t1, t2, t3,
                         Bs + (kk + l15) * 136 + wn * 32 + nh * 16 + lhi);
                bB[2 * nh][0] = t0; bB[2 * nh][1] = t1;
                bB[2 * nh + 1][0] = t2; bB[2 * nh + 1][1] = t3;
            }
            #pragma unroll
            for (int mt = 0; mt < 4; mt++)
                #pragma unroll
                for (int nt = 0; nt < 4; nt++)
                    mma_bf16(acc[mt][nt], aA[mt], bB[nt]);
        }
    }

    #pragma unroll
    for (int mt = 0; mt < 4; mt++) {
        int row = bm * 128 + wm * 64 + mt * 16 + gid;
        #pragma unroll
        for (int nt = 0; nt < 4; nt++) {
            int col = bn * 128 + wn * 32 + nt * 8 + 2 * tig;
            float bb0 = bias[col], bb1 = bias[col + 1];
            size_t i0 = (size_t)row * N + col;
            size_t i1 = i0 + 8 * (size_t)N;
            float v0 = acc[mt][nt][0] + bb0, v1 = acc[mt][nt][1] + bb1;
            float v2 = acc[mt][nt][2] + bb0, v3 = acc[mt][nt][3] + bb1;
            if (OUT_BF16) {
                __nv_bfloat16* C = (__nv_bfloat16*)outp;
                *reinterpret_cast<__nv_bfloat162*>(C + i0) = __floats2bfloat162_rn(v0, v1);
                *reinterpret_cast<__nv_bfloat162*>(C + i1) = __floats2bfloat162_rn(v2, v3);
            } else {
                float* C = (float*)outp;
                if (ADD_RES) { v0 += res[i0]; v1 += res[i0 + 1]; v2 += res[i1]; v3 += res[i1 + 1]; }
                C[i0] = v0; C[i0 + 1] = v1; C[i1] = v2; C[i1 + 1] = v3;
            }
        }
    }
}

// ---------------------------------------------------------------------------
// Flash attention over 2S keys. 128-row Q tile, 8 warps (256 thr).
// exp2-based softmax: Q pre-scaled by 0.125*log2(e); exp2f in softmax.
// K/V tiles (64 keys) double-buffered via cp.async, amortized over 8 warps.
// ---------------------------------------------------------------------------
#define AT_QROWS   128
#define AT_SMEM    ((AT_QROWS * 72 + 2 * 64 * 72 + 2 * 64 * 72) * 2)  // 55296 B

__global__ __launch_bounds__(256)
void attn_kernel()
{
    extern __shared__ __align__(16) __nv_bfloat16 sm[];
    __nv_bfloat16* Qs = sm;                       // [128][72]
    __nv_bfloat16* Kb = sm + AT_QROWS * 72;       // [2][64][72]
    __nv_bfloat16* Vb = Kb + 2 * 64 * 72;         // [2][64][72]

    const int qt = blockIdx.x, h = blockIdx.y, bfi = blockIdx.z;
    const int bf0 = bfi & ~(N_FR - 1);
    const int tid = threadIdx.x;
    const int w = tid >> 5, lane = tid & 31;
    const int gid = lane >> 2, tig = lane & 3;
    const int l15 = lane & 15, lhi = (lane >> 4) << 3;

    // Stage Q tile (128 rows), pre-scaled by 0.125 * log2(e)
    {
        const float qsc = 0.125f * 1.44269504f;
        #pragma unroll
        for (int i = 0; i < 4; i++) {
            int idx = tid + i * 256;
            int r = idx >> 3, c = (idx & 7) * 8;
            const __nv_bfloat16* p = g_q + (size_t)(bfi * SEQ + qt * AT_QROWS + r) * D_MODEL + h * HDIM + c;
            uint4 v = *reinterpret_cast<const uint4*>(p);
            __nv_bfloat16* pe = reinterpret_cast<__nv_bfloat16*>(&v);
            #pragma unroll
            for (int j = 0; j < 8; j++)
                pe[j] = __float2bfloat16_rn(__bfloat162float(pe[j]) * qsc);
            *reinterpret_cast<uint4*>(Qs + r * 72 + c) = v;
        }
    }

    auto stageKV = [&](int buf, int t) {
        const int sbf = (t < 16) ? bf0 : bfi;
        const int k0 = (t & 15) * 64;
        #pragma unroll
        for (int i = 0; i < 2; i++) {
            int idx = tid + i * 256;
            int r = idx >> 3, c = (idx & 7) * 8;
            size_t base = (size_t)(sbf * SEQ + k0 + r) * D_MODEL + h * HDIM + c;
            cp16(Kb + buf * 4608 + r * 72 + c, g_k + base);
            cp16(Vb + buf * 4608 + r * 72 + c, g_v + base);
        }
        cp_commit();
    };

    stageKV(0, 0);
    __syncthreads();

    // Hoist Q fragments (warp w -> rows w*16..w*16+15)
    uint32_t qf[4][4];
    #pragma unroll
    for (int kj = 0; kj < 4; kj++)
        ldm_x4(qf[kj][0], qf[kj][1], qf[kj][2], qf[kj][3],
               Qs + (w * 16 + l15) * 72 + kj * 16 + lhi);

    float oacc[8][4];
    #pragma unroll
    for (int nt = 0; nt < 8; nt++)
        #pragma unroll
        for (int i = 0; i < 4; i++) oacc[nt][i] = 0.f;
    float m0 = -3e38f, m1 = -3e38f, l0 = 0.f, l1 = 0.f;

    int buf = 0;
    for (int t = 0; t < 32; t++) {
        cp_wait0();
        __syncthreads();
        if (t + 1 < 32) stageKV(buf ^ 1, t + 1);

        // S = Q @ K^T (in log2 units): 16x64 per warp
        float sacc[8][4];
        #pragma unroll
        for (int nt = 0; nt < 8; nt++)
            #pragma unroll
            for (int i = 0; i < 4; i++) sacc[nt][i] = 0.f;

        #pragma unroll
        for (int ntp = 0; ntp < 4; ntp++) {
            #pragma unroll
            for (int kj = 0; kj < 4; kj++) {
                uint32_t t0, t1, t2, t3;
                ldm_x4(t0, t1, t2, t3, Kb + buf * 4608 + (ntp * 16 + l15) * 72 + kj * 16 + lhi);
                uint32_t be[2] = {t0, t2};
                uint32_t bo[2] = {t1, t3};
                mma_bf16(sacc[2 * ntp],     qf[kj], be);
                mma_bf16(sacc[2 * ntp + 1], qf[kj], bo);
            }
        }

        // Online softmax in base-2 (rows r0, r0+8)
        float mx0 = -3e38f, mx1 = -3e38f;
        #pragma unroll
        for (int nt = 0; nt < 8; nt++) {
            mx0 = fmaxf(mx0, fmaxf(sacc[nt][0], sacc[nt][1]));
            mx1 = fmaxf(mx1, fmaxf(sacc[nt][2], sacc[nt][3]));
        }
        mx0 = fmaxf(mx0, __shfl_xor_sync(0xffffffffu, mx0, 1));
        mx0 = fmaxf(mx0, __shfl_xor_sync(0xffffffffu, mx0, 2));
        mx1 = fmaxf(mx1, __shfl_xor_sync(0xffffffffu, mx1, 1));
        mx1 = fmaxf(mx1, __shfl_xor_sync(0xffffffffu, mx1, 2));

        float mn0 = fmaxf(m0, mx0), mn1 = fmaxf(m1, mx1);
        float a0 = exp2f(m0 - mn0), a1 = exp2f(m1 - mn1);
        float s0 = 0.f, s1 = 0.f;
        #pragma unroll
        for (int nt = 0; nt < 8; nt++) {
            float p0 = exp2f(sacc[nt][0] - mn0), p1 = exp2f(sacc[nt][1] - mn0);
            float p2 = exp2f(sacc[nt][2] - mn1), p3 = exp2f(sacc[nt][3] - mn1);
            s0 += p0 + p1; s1 += p2 + p3;
            sacc[nt][0] = p0; sacc[nt][1] = p1; sacc[nt][2] = p2; sacc[nt][3] = p3;
        }
        s0 += __shfl_xor_sync(0xffffffffu, s0, 1);
        s0 += __shfl_xor_sync(0xffffffffu, s0, 2);
        s1 += __shfl_xor_sync(0xffffffffu, s1, 1);
        s1 += __shfl_xor_sync(0xffffffffu, s1, 2);
        l0 = l0 * a0 + s0; l1 = l1 * a1 + s1;
        m0 = mn0; m1 = mn1;

        #pragma unroll
        for (int nt = 0; nt < 8; nt++) {
            oacc[nt][0] *= a0; oacc[nt][1] *= a0;
            oacc[nt][2] *= a1; oacc[nt][3] *= a1;
        }

        // O += P @ V
        #pragma unroll
        for (int kj = 0; kj < 4; kj++) {
            uint32_t ap[4];
            ap[0] = packbf(sacc[2 * kj][0],     sacc[2 * kj][1]);
            ap[1] = packbf(sacc[2 * kj][2],     sacc[2 * kj][3]);
            ap[2] = packbf(sacc[2 * kj + 1][0], sacc[2 * kj + 1][1]);
            ap[3] = packbf(sacc[2 * kj + 1][2], sacc[2 * kj + 1][3]);
            int vrow = kj * 16 + ((lane >> 3) & 1) * 8 + (lane & 7);
            #pragma unroll
            for (int dp = 0; dp < 4; dp++) {
                int vcol = dp * 16 + ((lane >> 4) & 1) * 8;
                uint32_t b0, b1, b2, b3;
                ldm_x4_t(b0, b1, b2, b3, Vb + buf * 4608 + vrow * 72 + vcol);
                uint32_t bb0[2] = {b0, b1};
                uint32_t bb1[2] = {b2, b3};
                mma_bf16(oacc[2 * dp],     ap, bb0);
                mma_bf16(oacc[2 * dp + 1], ap, bb1);
            }
        }
        buf ^= 1;
    }

    const int r0 = w * 16 + gid;
    const float inv0 = 1.f / l0, inv1 = 1.f / l1;
    #pragma unroll
    for (int nt = 0; nt < 8; nt++) {
        int dcol = h * HDIM + nt * 8 + 2 * tig;
        size_t b0 = (size_t)(bfi * SEQ + qt * AT_QROWS + r0) * D_MODEL + dcol;
        size_t b1 = b0 + 8 * (size_t)D_MODEL;
        *reinterpret_cast<__nv_bfloat162*>(g_attn + b0) =
            __floats2bfloat162_rn(oacc[nt][0] * inv0, oacc[nt][1] * inv0);
        *reinterpret_cast<__nv_bfloat162*>(g_attn + b1) =
            __floats2bfloat162_rn(oacc[nt][2] * inv1, oacc[nt][3] * inv1);
    }
}

// ---------------------------------------------------------------------------

extern "C" void kernel_launch(void* const* d_in, const int* in_sizes, int n_in,
                              void* d_out, int out_size)
{
    const float* hs = (const float*)d_in[0];
    const float* Wq = (const float*)d_in[1];
    const float* Wk = (const float*)d_in[2];
    const float* Wv = (const float*)d_in[3];
    const float* Wo = (const float*)d_in[4];
    const float* bq = (const float*)d_in[5];
    const float* bk = (const float*)d_in[6];
    const float* bv = (const float*)d_in[7];
    const float* bo = (const float*)d_in[8];
    float* out = (float*)d_out;

    __nv_bfloat16 *hsb, *wqb, *wkb, *wvb, *wob, *qp, *kp, *vp, *ap;
    cudaGetSymbolAddress((void**)&hsb, g_hs);
    cudaGetSymbolAddress((void**)&wqb, g_wq);
    cudaGetSymbolAddress((void**)&wkb, g_wk);
    cudaGetSymbolAddress((void**)&wvb, g_wv);
    cudaGetSymbolAddress((void**)&wob, g_wo);
    cudaGetSymbolAddress((void**)&qp, g_q);
    cudaGetSymbolAddress((void**)&kp, g_k);
    cudaGetSymbolAddress((void**)&vp, g_v);
    cudaGetSymbolAddress((void**)&ap, g_attn);

    const int n_hs = M_TOT * D_MODEL, n_w = D_MODEL * D_MODEL;
    cvt_kernel<<<n_hs / 4 / 256, 256>>>(hs, hsb, n_hs);
    cvt4_kernel<<<dim3(n_w / 4 / 256, 1, 4), 256>>>(Wq, Wk, Wv, Wo, wqb, wkb, wvb, wob, n_w);

    cudaFuncSetAttribute((const void*)gemm_kernel<true, false>,
                         cudaFuncAttributeMaxDynamicSharedMemorySize, G_SMEM);
    cudaFuncSetAttribute((const void*)gemm_kernel<false, true>,
                         cudaFuncAttributeMaxDynamicSharedMemorySize, G_SMEM);
    cudaFuncSetAttribute((const void*)attn_kernel,
                         cudaFuncAttributeMaxDynamicSharedMemorySize, AT_SMEM);

    // Fused QKV: grid.x = 30 (3 weights x 10 n-tiles)
    gemm_kernel<true, false><<<dim3(30, M_TOT / 128), 256, G_SMEM>>>(
        hsb, wqb, wkb, wvb, bq, bk, bv, qp, kp, vp, nullptr, M_TOT, D_MODEL, D_MODEL);

    attn_kernel<<<dim3(SEQ / AT_QROWS, N_HEADS, N_BF), 256, AT_SMEM>>>();

    gemm_kernel<false, true><<<dim3(10, M_TOT / 128), 256, G_SMEM>>>(
        ap, wob, wob, wob, bo, bo, bo, out, out, out, hs, M_TOT, D_MODEL, D_MODEL);
}

// round 9
// speedup vs baseline: 2.7112x; 1.0390x over previous
#include <cuda_runtime.h>
#include <cuda_bf16.h>
#include <cstdint>

#define D_MODEL 1280
#define SEQ     1024
#define N_BF    8
#define N_FR    4
#define N_HEADS 20
#define HDIM    64
#define M_TOT   (N_BF*SEQ)   // 8192

// Scratch (allocation-free rule: device globals). All bf16.
__device__ __nv_bfloat16 g_hs[(size_t)M_TOT * D_MODEL];
__device__ __nv_bfloat16 g_wq[(size_t)D_MODEL * D_MODEL];
__device__ __nv_bfloat16 g_wk[(size_t)D_MODEL * D_MODEL];
__device__ __nv_bfloat16 g_wv[(size_t)D_MODEL * D_MODEL];
__device__ __nv_bfloat16 g_wo[(size_t)D_MODEL * D_MODEL];
__device__ __nv_bfloat16 g_q[(size_t)M_TOT * D_MODEL];
__device__ __nv_bfloat16 g_k[(size_t)M_TOT * D_MODEL];
__device__ __nv_bfloat16 g_v[(size_t)M_TOT * D_MODEL];
__device__ __nv_bfloat16 g_attn[(size_t)M_TOT * D_MODEL];

__device__ __forceinline__ uint32_t packbf(float lo, float hi) {
    __nv_bfloat162 h = __floats2bfloat162_rn(lo, hi);
    return *reinterpret_cast<uint32_t*>(&h);
}

__device__ __forceinline__ void mma_bf16(float d[4], const uint32_t a[4], const uint32_t b[2]) {
    asm volatile(
        "mma.sync.aligned.m16n8k16.row.col.f32.bf16.bf16.f32 "
        "{%0,%1,%2,%3}, {%4,%5,%6,%7}, {%8,%9}, {%0,%1,%2,%3};\n"
        : "+f"(d[0]), "+f"(d[1]), "+f"(d[2]), "+f"(d[3])
        : "r"(a[0]), "r"(a[1]), "r"(a[2]), "r"(a[3]),
          "r"(b[0]), "r"(b[1]));
}

__device__ __forceinline__ void ldm_x4(uint32_t& r0, uint32_t& r1, uint32_t& r2, uint32_t& r3,
                                       const void* p) {
    uint32_t a = (uint32_t)__cvta_generic_to_shared(p);
    asm volatile("ldmatrix.sync.aligned.m8n8.x4.shared.b16 {%0,%1,%2,%3}, [%4];\n"
                 : "=r"(r0), "=r"(r1), "=r"(r2), "=r"(r3) : "r"(a));
}

__device__ __forceinline__ void ldm_x4_t(uint32_t& r0, uint32_t& r1, uint32_t& r2, uint32_t& r3,
                                         const void* p) {
    uint32_t a = (uint32_t)__cvta_generic_to_shared(p);
    asm volatile("ldmatrix.sync.aligned.m8n8.x4.trans.shared.b16 {%0,%1,%2,%3}, [%4];\n"
                 : "=r"(r0), "=r"(r1), "=r"(r2), "=r"(r3) : "r"(a));
}

__device__ __forceinline__ void cp16(void* smem, const void* gmem) {
    uint32_t s = (uint32_t)__cvta_generic_to_shared(smem);
    asm volatile("cp.async.cg.shared.global [%0], [%1], 16;\n" :: "r"(s), "l"(gmem));
}
__device__ __forceinline__ void cp_commit() { asm volatile("cp.async.commit_group;\n"); }
__device__ __forceinline__ void cp_wait0()  { asm volatile("cp.async.wait_group 0;\n"); }
__device__ __forceinline__ void cp_wait2()  { asm volatile("cp.async.wait_group 2;\n"); }

// ---------------------------------------------------------------------------
// fp32 -> bf16 converter
// ---------------------------------------------------------------------------
__global__ void cvt_kernel(const float* __restrict__ in, __nv_bfloat16* __restrict__ out, int n)
{
    int i = (blockIdx.x * blockDim.x + threadIdx.x) * 4;
    if (i >= n) return;
    float4 v = *reinterpret_cast<const float4*>(in + i);
    __nv_bfloat162 lo = __floats2bfloat162_rn(v.x, v.y);
    __nv_bfloat162 hi = __floats2bfloat162_rn(v.z, v.w);
    uint2 o = make_uint2(*reinterpret_cast<uint32_t*>(&lo), *reinterpret_cast<uint32_t*>(&hi));
    *reinterpret_cast<uint2*>(out + i) = o;
}

// Fused 4-weight converter (grid.z routes)
__global__ void cvt4_kernel(const float* __restrict__ s0, const float* __restrict__ s1,
                            const float* __restrict__ s2, const float* __restrict__ s3,
                            __nv_bfloat16* __restrict__ d0, __nv_bfloat16* __restrict__ d1,
                            __nv_bfloat16* __restrict__ d2, __nv_bfloat16* __restrict__ d3,
                            int n)
{
    const float* in = (blockIdx.z == 0) ? s0 : (blockIdx.z == 1) ? s1
                    : (blockIdx.z == 2) ? s2 : s3;
    __nv_bfloat16* out = (blockIdx.z == 0) ? d0 : (blockIdx.z == 1) ? d1
                       : (blockIdx.z == 2) ? d2 : d3;
    int i = (blockIdx.x * blockDim.x + threadIdx.x) * 4;
    if (i >= n) return;
    float4 v = *reinterpret_cast<const float4*>(in + i);
    __nv_bfloat162 lo = __floats2bfloat162_rn(v.x, v.y);
    __nv_bfloat162 hi = __floats2bfloat162_rn(v.z, v.w);
    uint2 o = make_uint2(*reinterpret_cast<uint32_t*>(&lo), *reinterpret_cast<uint32_t*>(&hi));
    *reinterpret_cast<uint2*>(out + i) = o;
}

// ---------------------------------------------------------------------------
// GEMM (unchanged from round 7/8 best).
// ---------------------------------------------------------------------------
#define GK_NSTG   (D_MODEL / 32)   // 40
#define GA_ELEMS  (128 * 40)
#define GB_ELEMS  (32 * 136)
#define G_SMEM    ((4 * GA_ELEMS + 4 * GB_ELEMS) * 2)   // 75776 B

template<bool OUT_BF16, bool ADD_RES>
__global__ __launch_bounds__(256, 2)
void gemm_kernel(const __nv_bfloat16* __restrict__ A,
                 const __nv_bfloat16* __restrict__ W0, const __nv_bfloat16* __restrict__ W1,
                 const __nv_bfloat16* __restrict__ W2,
                 const float* __restrict__ b0, const float* __restrict__ b1,
                 const float* __restrict__ b2,
                 void* __restrict__ o0, void* __restrict__ o1, void* __restrict__ o2,
                 const float* __restrict__ res, int M, int N, int K)
{
    extern __shared__ __align__(16) char smem[];
    __nv_bfloat16* Abase = reinterpret_cast<__nv_bfloat16*>(smem);
    __nv_bfloat16* Bbase = Abase + 4 * GA_ELEMS;

    const int bm = blockIdx.y;
    const int which = blockIdx.x / 10, bn = blockIdx.x % 10;
    const __nv_bfloat16* W = (which == 0) ? W0 : (which == 1) ? W1 : W2;
    const float* bias = (which == 0) ? b0 : (which == 1) ? b1 : b2;
    void* outp = (which == 0) ? o0 : (which == 1) ? o1 : o2;

    const int tid = threadIdx.x;
    const int warp = tid >> 5, lane = tid & 31;
    const int wm = warp >> 2, wn = warp & 3;
    const int gid = lane >> 2, tig = lane & 3;
    const int l15 = lane & 15, lhi = (lane >> 4) << 3;

    float acc[4][4][4];
    #pragma unroll
    for (int mt = 0; mt < 4; mt++)
        #pragma unroll
        for (int nt = 0; nt < 4; nt++)
            #pragma unroll
            for (int i = 0; i < 4; i++) acc[mt][nt][i] = 0.f;

    auto stage = [&](int s) {
        const int buf = s & 3;
        const int kt = s * 32;
        __nv_bfloat16* As = Abase + buf * GA_ELEMS;
        __nv_bfloat16* Bs = Bbase + buf * GB_ELEMS;
        #pragma unroll
        for (int i = 0; i < 2; i++) {
            int idx = tid + i * 256;
            int r = idx >> 2, c = (idx & 3) * 8;
            cp16(As + r * 40 + c, A + (size_t)(bm * 128 + r) * K + kt + c);
        }
        #pragma unroll
        for (int i = 0; i < 2; i++) {
            int idx = tid + i * 256;
            int r = idx >> 4, c = (idx & 15) * 8;
            cp16(Bs + r * 136 + c, W + (size_t)(kt + r) * N + bn * 128 + c);
        }
        cp_commit();
    };

    stage(0); stage(1); stage(2);

    for (int s = 0; s < GK_NSTG; s++) {
        cp_wait2();
        __syncthreads();
        if (s + 3 < GK_NSTG) stage(s + 3);
        else cp_commit();

        const int buf = s & 3;
        const __nv_bfloat16* As = Abase + buf * GA_ELEMS;
        const __nv_bfloat16* Bs = Bbase + buf * GB_ELEMS;

        #pragma unroll
        for (int kk = 0; kk < 32; kk += 16) {
            uint32_t aA[4][4];
            #pragma unroll
            for (int mt = 0; mt < 4; mt++)
                ldm_x4(aA[mt][0], aA[mt][1], aA[mt][2], aA[mt][3],
                       As + (wm * 64 + mt * 16 + l15) * 40 + kk + lhi);
            uint32_t bB[4][2];
            #pragma unroll
            for (int nh = 0; nh < 2; nh++) {
                uint32_t t0, t1, t2, t3;
                ldm_x4_t(t0, t1, t2, t3,
                         Bs + (kk + l15) * 136 + wn * 32 + nh * 16 + lhi);
                bB[2 * nh][0] = t0; bB[2 * nh][1] = t1;
                bB[2 * nh + 1][0] = t2; bB[2 * nh + 1][1] = t3;
            }
            #pragma unroll
            for (int mt = 0; mt < 4; mt++)
                #pragma unroll
                for (int nt = 0; nt < 4; nt++)
                    mma_bf16(acc[mt][nt], aA[mt], bB[nt]);
        }
    }

    #pragma unroll
    for (int mt = 0; mt < 4; mt++) {
        int row = bm * 128 + wm * 64 + mt * 16 + gid;
        #pragma unroll
        for (int nt = 0; nt < 4; nt++) {
            int col = bn * 128 + wn * 32 + nt * 8 + 2 * tig;
            float bb0 = bias[col], bb1 = bias[col + 1];
            size_t i0 = (size_t)row * N + col;
            size_t i1 = i0 + 8 * (size_t)N;
            float v0 = acc[mt][nt][0] + bb0, v1 = acc[mt][nt][1] + bb1;
            float v2 = acc[mt][nt][2] + bb0, v3 = acc[mt][nt][3] + bb1;
            if (OUT_BF16) {
                __nv_bfloat16* C = (__nv_bfloat16*)outp;
                *reinterpret_cast<__nv_bfloat162*>(C + i0) = __floats2bfloat162_rn(v0, v1);
                *reinterpret_cast<__nv_bfloat162*>(C + i1) = __floats2bfloat162_rn(v2, v3);
            } else {
                float* C = (float*)outp;
                if (ADD_RES) { v0 += res[i0]; v1 += res[i0 + 1]; v2 += res[i1]; v3 += res[i1 + 1]; }
                C[i0] = v0; C[i0 + 1] = v1; C[i1] = v2; C[i1 + 1] = v3;
            }
        }
    }
}

// ---------------------------------------------------------------------------
// Flash attention over 2S keys. 128-row Q tile, 4 warps (128 thr); each warp
// owns TWO m16 row-groups (32 Q rows) so every K/V ldmatrix fragment feeds
// 2x the MMAs -> smem crossbar traffic per MMA halves (the measured limiter).
// exp2-domain softmax (Q pre-scaled by 0.125*log2 e).
// ---------------------------------------------------------------------------
#define AT_QROWS   128
#define AT_SMEM    ((AT_QROWS * 72 + 2 * 64 * 72 + 2 * 64 * 72) * 2)  // 55296 B

__global__ __launch_bounds__(128)
void attn_kernel()
{
    extern __shared__ __align__(16) __nv_bfloat16 sm[];
    __nv_bfloat16* Qs = sm;                       // [128][72]
    __nv_bfloat16* Kb = sm + AT_QROWS * 72;       // [2][64][72]
    __nv_bfloat16* Vb = Kb + 2 * 64 * 72;         // [2][64][72]

    const int qt = blockIdx.x, h = blockIdx.y, bfi = blockIdx.z;
    const int bf0 = bfi & ~(N_FR - 1);
    const int tid = threadIdx.x;
    const int w = tid >> 5, lane = tid & 31;
    const int gid = lane >> 2, tig = lane & 3;
    const int l15 = lane & 15, lhi = (lane >> 4) << 3;

    // Stage Q tile (128 rows), pre-scaled by 0.125 * log2(e)
    {
        const float qsc = 0.125f * 1.44269504f;
        #pragma unroll
        for (int i = 0; i < 8; i++) {
            int idx = tid + i * 128;
            int r = idx >> 3, c = (idx & 7) * 8;
            const __nv_bfloat16* p = g_q + (size_t)(bfi * SEQ + qt * AT_QROWS + r) * D_MODEL + h * HDIM + c;
            uint4 v = *reinterpret_cast<const uint4*>(p);
            __nv_bfloat16* pe = reinterpret_cast<__nv_bfloat16*>(&v);
            #pragma unroll
            for (int j = 0; j < 8; j++)
                pe[j] = __float2bfloat16_rn(__bfloat162float(pe[j]) * qsc);
            *reinterpret_cast<uint4*>(Qs + r * 72 + c) = v;
        }
    }

    auto stageKV = [&](int buf, int t) {
        const int sbf = (t < 16) ? bf0 : bfi;
        const int k0 = (t & 15) * 64;
        #pragma unroll
        for (int i = 0; i < 4; i++) {
            int idx = tid + i * 128;
            int r = idx >> 3, c = (idx & 7) * 8;
            size_t base = (size_t)(sbf * SEQ + k0 + r) * D_MODEL + h * HDIM + c;
            cp16(Kb + buf * 4608 + r * 72 + c, g_k + base);
            cp16(Vb + buf * 4608 + r * 72 + c, g_v + base);
        }
        cp_commit();
    };

    stageKV(0, 0);
    __syncthreads();

    // Hoist Q fragments for BOTH row-groups: g0 rows w*16.., g1 rows 64+w*16..
    uint32_t qf[2][4][4];
    #pragma unroll
    for (int g = 0; g < 2; g++)
        #pragma unroll
        for (int kj = 0; kj < 4; kj++)
            ldm_x4(qf[g][kj][0], qf[g][kj][1], qf[g][kj][2], qf[g][kj][3],
                   Qs + (g * 64 + w * 16 + l15) * 72 + kj * 16 + lhi);

    float oacc[2][8][4];
    #pragma unroll
    for (int g = 0; g < 2; g++)
        #pragma unroll
        for (int nt = 0; nt < 8; nt++)
            #pragma unroll
            for (int i = 0; i < 4; i++) oacc[g][nt][i] = 0.f;
    float mrow[2][2] = {{-3e38f, -3e38f}, {-3e38f, -3e38f}};
    float lrow[2][2] = {{0.f, 0.f}, {0.f, 0.f}};

    int buf = 0;
    for (int t = 0; t < 32; t++) {
        cp_wait0();
        __syncthreads();
        if (t + 1 < 32) stageKV(buf ^ 1, t + 1);

        // S = Q @ K^T (log2 units): 32x64 per warp; K frag loaded ONCE per 2 groups
        float sacc[2][8][4];
        #pragma unroll
        for (int g = 0; g < 2; g++)
            #pragma unroll
            for (int nt = 0; nt < 8; nt++)
                #pragma unroll
                for (int i = 0; i < 4; i++) sacc[g][nt][i] = 0.f;

        #pragma unroll
        for (int ntp = 0; ntp < 4; ntp++) {
            #pragma unroll
            for (int kj = 0; kj < 4; kj++) {
                uint32_t t0, t1, t2, t3;
                ldm_x4(t0, t1, t2, t3, Kb + buf * 4608 + (ntp * 16 + l15) * 72 + kj * 16 + lhi);
                uint32_t be[2] = {t0, t2};
                uint32_t bo[2] = {t1, t3};
                #pragma unroll
                for (int g = 0; g < 2; g++) {
                    mma_bf16(sacc[g][2 * ntp],     qf[g][kj], be);
                    mma_bf16(sacc[g][2 * ntp + 1], qf[g][kj], bo);
                }
            }
        }

        // Online softmax (base-2), per group
        float a01[2][2];
        #pragma unroll
        for (int g = 0; g < 2; g++) {
            float mx0 = -3e38f, mx1 = -3e38f;
            #pragma unroll
            for (int nt = 0; nt < 8; nt++) {
                mx0 = fmaxf(mx0, fmaxf(sacc[g][nt][0], sacc[g][nt][1]));
                mx1 = fmaxf(mx1, fmaxf(sacc[g][nt][2], sacc[g][nt][3]));
            }
            mx0 = fmaxf(mx0, __shfl_xor_sync(0xffffffffu, mx0, 1));
            mx0 = fmaxf(mx0, __shfl_xor_sync(0xffffffffu, mx0, 2));
            mx1 = fmaxf(mx1, __shfl_xor_sync(0xffffffffu, mx1, 1));
            mx1 = fmaxf(mx1, __shfl_xor_sync(0xffffffffu, mx1, 2));

            float mn0 = fmaxf(mrow[g][0], mx0), mn1 = fmaxf(mrow[g][1], mx1);
            float a0 = exp2f(mrow[g][0] - mn0), a1 = exp2f(mrow[g][1] - mn1);
            float s0 = 0.f, s1 = 0.f;
            #pragma unroll
            for (int nt = 0; nt < 8; nt++) {
                float p0 = exp2f(sacc[g][nt][0] - mn0), p1 = exp2f(sacc[g][nt][1] - mn0);
                float p2 = exp2f(sacc[g][nt][2] - mn1), p3 = exp2f(sacc[g][nt][3] - mn1);
                s0 += p0 + p1; s1 += p2 + p3;
                sacc[g][nt][0] = p0; sacc[g][nt][1] = p1;
                sacc[g][nt][2] = p2; sacc[g][nt][3] = p3;
            }
            s0 += __shfl_xor_sync(0xffffffffu, s0, 1);
            s0 += __shfl_xor_sync(0xffffffffu, s0, 2);
            s1 += __shfl_xor_sync(0xffffffffu, s1, 1);
            s1 += __shfl_xor_sync(0xffffffffu, s1, 2);
            lrow[g][0] = lrow[g][0] * a0 + s0; lrow[g][1] = lrow[g][1] * a1 + s1;
            mrow[g][0] = mn0; mrow[g][1] = mn1;
            a01[g][0] = a0; a01[g][1] = a1;
        }

        #pragma unroll
        for (int g = 0; g < 2; g++)
            #pragma unroll
            for (int nt = 0; nt < 8; nt++) {
                oacc[g][nt][0] *= a01[g][0]; oacc[g][nt][1] *= a01[g][0];
                oacc[g][nt][2] *= a01[g][1]; oacc[g][nt][3] *= a01[g][1];
            }

        // O += P @ V : V frag loaded ONCE per 2 groups
        #pragma unroll
        for (int kj = 0; kj < 4; kj++) {
            uint32_t ap[2][4];
            #pragma unroll
            for (int g = 0; g < 2; g++) {
                ap[g][0] = packbf(sacc[g][2 * kj][0],     sacc[g][2 * kj][1]);
                ap[g][1] = packbf(sacc[g][2 * kj][2],     sacc[g][2 * kj][3]);
                ap[g][2] = packbf(sacc[g][2 * kj + 1][0], sacc[g][2 * kj + 1][1]);
                ap[g][3] = packbf(sacc[g][2 * kj + 1][2], sacc[g][2 * kj + 1][3]);
            }
            int vrow = kj * 16 + ((lane >> 3) & 1) * 8 + (lane & 7);
            #pragma unroll
            for (int dp = 0; dp < 4; dp++) {
                int vcol = dp * 16 + ((lane >> 4) & 1) * 8;
                uint32_t b0, b1, b2, b3;
                ldm_x4_t(b0, b1, b2, b3, Vb + buf * 4608 + vrow * 72 + vcol);
                uint32_t bb0[2] = {b0, b1};
                uint32_t bb1[2] = {b2, b3};
                #pragma unroll
                for (int g = 0; g < 2; g++) {
                    mma_bf16(oacc[g][2 * dp],     ap[g], bb0);
                    mma_bf16(oacc[g][2 * dp + 1], ap[g], bb1);
                }
            }
        }
        buf ^= 1;
    }

    #pragma unroll
    for (int g = 0; g < 2; g++) {
        const int r0 = g * 64 + w * 16 + gid;
        const float inv0 = 1.f / lrow[g][0], inv1 = 1.f / lrow[g][1];
        #pragma unroll
        for (int nt = 0; nt < 8; nt++) {
            int dcol = h * HDIM + nt * 8 + 2 * tig;
            size_t b0 = (size_t)(bfi * SEQ + qt * AT_QROWS + r0) * D_MODEL + dcol;
            size_t b1 = b0 + 8 * (size_t)D_MODEL;
            *reinterpret_cast<__nv_bfloat162*>(g_attn + b0) =
                __floats2bfloat162_rn(oacc[g][nt][0] * inv0, oacc[g][nt][1] * inv0);
            *reinterpret_cast<__nv_bfloat162*>(g_attn + b1) =
                __floats2bfloat162_rn(oacc[g][nt][2] * inv1, oacc[g][nt][3] * inv1);
        }
    }
}

// ---------------------------------------------------------------------------

extern "C" void kernel_launch(void* const* d_in, const int* in_sizes, int n_in,
                              void* d_out, int out_size)
{
    const float* hs = (const float*)d_in[0];
    const float* Wq = (const float*)d_in[1];
    const float* Wk = (const float*)d_in[2];
    const float* Wv = (const float*)d_in[3];
    const float* Wo = (const float*)d_in[4];
    const float* bq = (const float*)d_in[5];
    const float* bk = (const float*)d_in[6];
    const float* bv = (const float*)d_in[7];
    const float* bo = (const float*)d_in[8];
    float* out = (float*)d_out;

    __nv_bfloat16 *hsb, *wqb, *wkb, *wvb, *wob, *qp, *kp, *vp, *ap;
    cudaGetSymbolAddress((void**)&hsb, g_hs);
    cudaGetSymbolAddress((void**)&wqb, g_wq);
    cudaGetSymbolAddress((void**)&wkb, g_wk);
    cudaGetSymbolAddress((void**)&wvb, g_wv);
    cudaGetSymbolAddress((void**)&wob, g_wo);
    cudaGetSymbolAddress((void**)&qp, g_q);
    cudaGetSymbolAddress((void**)&kp, g_k);
    cudaGetSymbolAddress((void**)&vp, g_v);
    cudaGetSymbolAddress((void**)&ap, g_attn);

    const int n_hs = M_TOT * D_MODEL, n_w = D_MODEL * D_MODEL;
    cvt_kernel<<<n_hs / 4 / 256, 256>>>(hs, hsb, n_hs);
    cvt4_kernel<<<dim3(n_w / 4 / 256, 1, 4), 256>>>(Wq, Wk, Wv, Wo, wqb, wkb, wvb, wob, n_w);

    cudaFuncSetAttribute((const void*)gemm_kernel<true, false>,
                         cudaFuncAttributeMaxDynamicSharedMemorySize, G_SMEM);
    cudaFuncSetAttribute((const void*)gemm_kernel<false, true>,
                         cudaFuncAttributeMaxDynamicSharedMemorySize, G_SMEM);
    cudaFuncSetAttribute((const void*)attn_kernel,
                         cudaFuncAttributeMaxDynamicSharedMemorySize, AT_SMEM);

    // Fused QKV: grid.x = 30 (3 weights x 10 n-tiles)
    gemm_kernel<true, false><<<dim3(30, M_TOT / 128), 256, G_SMEM>>>(
        hsb, wqb, wkb, wvb, bq, bk, bv, qp, kp, vp, nullptr, M_TOT, D_MODEL, D_MODEL);

    attn_kernel<<<dim3(SEQ / AT_QROWS, N_HEADS, N_BF), 128, AT_SMEM>>>();

    gemm_kernel<false, true><<<dim3(10, M_TOT / 128), 256, G_SMEM>>>(
        ap, wob, wob, wob, bo, bo, bo, out, out, out, hs, M_TOT, D_MODEL, D_MODEL);
}